// round 9
// baseline (speedup 1.0000x reference)
#include <cuda_runtime.h>
#include <math.h>
#include <stdint.h>

// Problem constants
#define NROWS 32768   // B*H*W
#define DDIM  64
#define MCODE 1024
#define HWSZ  1024
#define ZQ_ELEMS 2097152

// Static device scratch
__device__ float g_b1[2 * NROWS];        // per code-half: best approx key
__device__ float g_b2[2 * NROWS];        // per code-half: 2nd-best approx key
__device__ float g_i1[2 * NROWS];        // per code-half: best idx (float)
__device__ float g_x2[NROWS];            // per-row squared norm
__device__ float g_find[NROWS];          // final argmin idx (float)
__device__ float g_y2[MCODE];
__device__ int   g_y2max_i = 0;          // max y2 as int bits (positive floats)
__device__ unsigned long long g_lacc = 0ull;  // fixed-point sum of s^2 (scale 2^22)
__device__ int   g_ctr = 0;              // zq completion counter (self-resetting)
// Codebook hi-tf32, fragment order: [chunk(16)][s(8)][ci(64)][t(4)] uint2{h0,h1}
__device__ uint2 g_bh[16 * 2048];

// ---------------------------------------------------------------------------
// helpers
// ---------------------------------------------------------------------------
__device__ __forceinline__ uint32_t f2tf32(float a) {
    uint32_t r; asm("cvt.rna.tf32.f32 %0, %1;" : "=r"(r) : "f"(a)); return r;
}
__device__ __forceinline__ uint32_t smem_u32(const void* p) {
    uint32_t a;
    asm("{ .reg .u64 t; cvta.to.shared.u64 t, %1; cvt.u32.u64 %0, t; }"
        : "=r"(a) : "l"(p));
    return a;
}
__device__ __forceinline__ void bulk_g2s(uint32_t dst, const void* src,
                                         uint32_t bytes, uint32_t mbar) {
    asm volatile(
        "cp.async.bulk.shared::cta.global.mbarrier::complete_tx::bytes [%0], [%1], %2, [%3];"
        :: "r"(dst), "l"(src), "r"(bytes), "r"(mbar) : "memory");
}
__device__ __forceinline__ void mbar_init(uint32_t mbar, uint32_t cnt) {
    asm volatile("mbarrier.init.shared.b64 [%0], %1;" :: "r"(mbar), "r"(cnt) : "memory");
}
__device__ __forceinline__ void mbar_expect_tx(uint32_t mbar, uint32_t bytes) {
    asm volatile("mbarrier.arrive.expect_tx.shared.b64 _, [%0], %1;"
                 :: "r"(mbar), "r"(bytes) : "memory");
}
__device__ __forceinline__ void mbar_wait(uint32_t mbar, uint32_t parity) {
    uint32_t done;
    asm volatile(
        "{\n\t.reg .pred p;\n\t"
        "mbarrier.try_wait.parity.acquire.cta.shared::cta.b64 p, [%1], %2;\n\t"
        "selp.b32 %0, 1, 0, p;\n\t}"
        : "=r"(done) : "r"(mbar), "r"(parity) : "memory");
    while (!done) {
        asm volatile(
            "{\n\t.reg .pred p;\n\t"
            "mbarrier.try_wait.parity.acquire.cta.shared::cta.b64 p, [%1], %2, 0x989680;\n\t"
            "selp.b32 %0, 1, 0, p;\n\t}"
            : "=r"(done) : "r"(mbar), "r"(parity) : "memory");
    }
}
// D = A(16x8) * B(8x8) + C, tf32, fp32 accum
__device__ __forceinline__ void mma16n8k8(float* c, uint32_t a0, uint32_t a1,
                                          uint32_t a2, uint32_t a3,
                                          uint32_t b0, uint32_t b1) {
    asm volatile(
        "mma.sync.aligned.m16n8k8.row.col.f32.tf32.tf32.f32 "
        "{%0,%1,%2,%3}, {%4,%5,%6,%7}, {%8,%9}, {%0,%1,%2,%3};"
        : "+f"(c[0]), "+f"(c[1]), "+f"(c[2]), "+f"(c[3])
        : "r"(a0), "r"(a1), "r"(a2), "r"(a3), "r"(b0), "r"(b1));
}

// ---------------------------------------------------------------------------
// Kernel 1: pack codebook (hi tf32 only) + per-code y2 + y2max.
// ---------------------------------------------------------------------------
__global__ void bprep_kernel(const float* __restrict__ cb) {
    int g = blockIdx.x * 256 + threadIdx.x;
    int c = g >> 5, s = (g >> 2) & 7, t = g & 3;
    float v0 = cb[c * DDIM + s * 8 + t];
    float v1 = cb[c * DDIM + s * 8 + t + 4];
    uint32_t h0 = f2tf32(v0), h1 = f2tf32(v1);
    int chunk = c >> 6, ci = c & 63;
    g_bh[chunk * 2048 + s * 256 + ci * 4 + t] = make_uint2(h0, h1);
    float y = v0 * v0 + v1 * v1;
    #pragma unroll
    for (int d = 16; d > 0; d >>= 1)
        y += __shfl_xor_sync(0xffffffffu, y, d);
    if ((threadIdx.x & 31) == 0) {
        g_y2[c] = y;
        atomicMax(&g_y2max_i, __float_as_int(y));
    }
}

// ---------------------------------------------------------------------------
// Kernel 2: 1-pass TF32 mma.sync GEMM + best/2nd-best argmin tracking.
// Grid 128: bit0 = code half (512 codes), bits1+ = row block (512 rows).
// 512 threads = 16 warps x 32 rows. 8 chunks of 64 codes, B double-buffered.
// smem: mbar | y2[512] | A (hi tf32 pairs, 128KB) | B 2x16KB.
// ---------------------------------------------------------------------------
#define SM_MB   0
#define SM_Y2   128
#define SM_A    2176
#define SM_B    133248
#define GEMM_SMEM 166016

__global__ __launch_bounds__(512, 1)
void gemm_argmin_kernel(const float* __restrict__ z) {
    extern __shared__ char sm[];
    uint32_t sb = smem_u32(sm);
    uint2* A2 = (uint2*)(sm + SM_A);
    const float* y2s = (const float*)(sm + SM_Y2);
    int tid = threadIdx.x;
    int wid = tid >> 5, lane = tid & 31;
    int g = lane >> 2, tt = lane & 3;
    int half = blockIdx.x & 1;
    int rb = blockIdx.x >> 1;            // 0..63
    int r0 = rb * 512;
    int w32 = wid * 32;
    const uint2* bsrc = g_bh + half * 16384;   // 8 chunks x 2048 uint2

    if (tid == 0) {
        mbar_init(sb + SM_MB + 0, 1);
        mbar_init(sb + SM_MB + 8, 1);
    }
    __syncthreads();

    if (tid == 0) {
        mbar_expect_tx(sb + SM_MB + 0, 16384);
        bulk_g2s(sb + SM_B, bsrc, 16384, sb + SM_MB + 0);
        mbar_expect_tx(sb + SM_MB + 8, 16384);
        bulk_g2s(sb + SM_B + 16384, bsrc + 2048, 16384, sb + SM_MB + 8);
    }

    // A prep: z[b, d, hw0 + r] -> hi-tf32 pairs + per-row x2 (half 0 writes)
    {
        const float* zb = z + (size_t)(rb >> 1) * (DDIM * HWSZ) + (rb & 1) * 512;
        int roff = lane >> 2, tp = lane & 3;
        #pragma unroll
        for (int p = 0; p < 4; ++p) {
            int r = p * 128 + wid * 8 + roff;
            float sq = 0.f;
            #pragma unroll
            for (int s = 0; s < 8; ++s) {
                float v0 = zb[(s * 8 + tp) * HWSZ + r];
                float v1 = zb[(s * 8 + tp + 4) * HWSZ + r];
                sq += v0 * v0 + v1 * v1;
                A2[(s * 512 + r) * 4 + tp] = make_uint2(f2tf32(v0), f2tf32(v1));
            }
            sq += __shfl_xor_sync(0xffffffffu, sq, 1);
            sq += __shfl_xor_sync(0xffffffffu, sq, 2);
            if (tp == 0 && half == 0) g_x2[r0 + r] = sq;
        }
    }
    for (int i = tid; i < 512; i += 512)
        ((float*)(sm + SM_Y2))[i] = g_y2[half * 512 + i];
    __syncthreads();

    float best[4], bst2[4];
    int   bidx[4];
    #pragma unroll
    for (int i = 0; i < 4; ++i) { best[i] = 3.4028235e38f; bst2[i] = 3.4028235e38f; bidx[i] = 0; }

    for (int ch = 0; ch < 8; ++ch) {
        int buf = ch & 1;
        mbar_wait(sb + SM_MB + buf * 8, (ch >> 1) & 1);
        const uint2* Bb = (const uint2*)(sm + SM_B + buf * 16384);

        float acc[2][8][4];
        #pragma unroll
        for (int m = 0; m < 2; ++m)
            #pragma unroll
            for (int j = 0; j < 8; ++j)
                #pragma unroll
                for (int e = 0; e < 4; ++e) acc[m][j][e] = 0.f;

        #pragma unroll
        for (int s = 0; s < 8; ++s) {
            uint2 a0 = A2[(s * 512 + w32 + g) * 4 + tt];
            uint2 a1 = A2[(s * 512 + w32 + 8 + g) * 4 + tt];
            uint2 a2 = A2[(s * 512 + w32 + 16 + g) * 4 + tt];
            uint2 a3 = A2[(s * 512 + w32 + 24 + g) * 4 + tt];
            #pragma unroll
            for (int j = 0; j < 8; ++j) {
                uint2 bq = Bb[s * 256 + (j * 8 + g) * 4 + tt];
                mma16n8k8(acc[0][j], a0.x, a1.x, a0.y, a1.y, bq.x, bq.y);
                mma16n8k8(acc[1][j], a2.x, a3.x, a2.y, a3.y, bq.x, bq.y);
            }
        }

        // epilogue: key = y2 - 2*dot; track best + second-best per row slot
        #pragma unroll
        for (int j = 0; j < 8; ++j) {
            int cl = ch * 64 + j * 8 + 2 * tt;
            float2 y = ((const float2*)y2s)[cl >> 1];
            #pragma unroll
            for (int m = 0; m < 2; ++m) {
                float k0 = fmaf(acc[m][j][0], -2.0f, y.x);
                float k1 = fmaf(acc[m][j][1], -2.0f, y.y);
                float k2 = fmaf(acc[m][j][2], -2.0f, y.x);
                float k3 = fmaf(acc[m][j][3], -2.0f, y.y);
                int s0 = m * 2, s1 = m * 2 + 1;
                if (k0 < best[s0]) { bst2[s0] = best[s0]; best[s0] = k0; bidx[s0] = cl; }
                else if (k0 < bst2[s0]) bst2[s0] = k0;
                if (k1 < best[s0]) { bst2[s0] = best[s0]; best[s0] = k1; bidx[s0] = cl + 1; }
                else if (k1 < bst2[s0]) bst2[s0] = k1;
                if (k2 < best[s1]) { bst2[s1] = best[s1]; best[s1] = k2; bidx[s1] = cl; }
                else if (k2 < bst2[s1]) bst2[s1] = k2;
                if (k3 < best[s1]) { bst2[s1] = best[s1]; best[s1] = k3; bidx[s1] = cl + 1; }
                else if (k3 < bst2[s1]) bst2[s1] = k3;
            }
        }

        __syncthreads();
        if (ch + 2 < 8 && tid == 0) {
            mbar_expect_tx(sb + SM_MB + buf * 8, 16384);
            bulk_g2s(sb + SM_B + buf * 16384, bsrc + (ch + 2) * 2048, 16384,
                     sb + SM_MB + buf * 8);
        }
    }

    // cross-lane merge of (best, idx, best2) over the 4 tt lanes
    #pragma unroll
    for (int m = 0; m < 4; ++m) {
        float b1 = best[m], b2 = bst2[m];
        int i1 = bidx[m];
        #pragma unroll
        for (int d = 1; d < 4; d <<= 1) {
            float ob1 = __shfl_xor_sync(0xffffffffu, b1, d);
            int   oi1 = __shfl_xor_sync(0xffffffffu, i1, d);
            float ob2 = __shfl_xor_sync(0xffffffffu, b2, d);
            float nb2 = fminf(fmaxf(b1, ob1), fminf(b2, ob2));
            if (ob1 < b1 || (ob1 == b1 && oi1 < i1)) { b1 = ob1; i1 = oi1; }
            b2 = nb2;
        }
        if (tt == 0) {
            int row = r0 + w32 + (m >> 1) * 16 + (m & 1) * 8 + g;
            g_b1[half * NROWS + row] = b1;
            g_b2[half * NROWS + row] = b2;
            g_i1[half * NROWS + row] = (float)(half * 512 + i1);
        }
    }
}

// ---------------------------------------------------------------------------
// Kernel 3: merge halves, margin test, exact fp32 fallback for ambiguous rows.
// 256 CTAs x 256 threads; CTA owns rows [blk*128, blk*128+128).
// ---------------------------------------------------------------------------
__global__ __launch_bounds__(256)
void fix_kernel(const float* __restrict__ z, const float* __restrict__ cb) {
    __shared__ float zsm[64];
    __shared__ int   list[128];
    __shared__ int   lcount;
    __shared__ float rval[256];
    __shared__ int   ridx[256];
    int t = threadIdx.x;
    int base = blockIdx.x * 128;
    if (t == 0) lcount = 0;
    __syncthreads();

    if (t < 128) {
        int n = base + t;
        float b10 = g_b1[n],         b11 = g_b1[NROWS + n];
        float b20 = g_b2[n],         b21 = g_b2[NROWS + n];
        float i10 = g_i1[n],         i11 = g_i1[NROWS + n];
        float fb, fi, fs;
        if (b11 < b10) { fb = b11; fi = i11; fs = fminf(b10, b21); }
        else           { fb = b10; fi = i10; fs = fminf(b11, b20); }
        float y2max = __int_as_float(g_y2max_i);
        float eps = 0.006f * sqrtf(g_x2[n] * y2max) + 1e-3f;
        if (fs - fb > eps) {
            g_find[n] = fi;
        } else {
            int sl = atomicAdd(&lcount, 1);
            list[sl] = t;
        }
    }
    __syncthreads();
    int cnt = lcount;

    for (int w = 0; w < cnt; ++w) {
        int n = base + list[w];
        if (t < 64) {
            int b = n >> 10, hw = n & 1023;
            zsm[t] = z[(size_t)b * 65536 + t * 1024 + hw];
        }
        __syncthreads();
        float bv = 3.4028235e38f;
        int bi = 0x7fffffff;
        for (int c = t; c < MCODE; c += 256) {
            const float* cr = cb + c * 64;
            float dot = 0.f;
            #pragma unroll
            for (int k = 0; k < 64; ++k) dot = fmaf(zsm[k], cr[k], dot);
            float key = fmaf(dot, -2.0f, g_y2[c]);
            if (key < bv) { bv = key; bi = c; }   // ascending c => first occurrence
        }
        rval[t] = bv; ridx[t] = bi;
        __syncthreads();
        for (int off = 128; off > 0; off >>= 1) {
            if (t < off) {
                float v2 = rval[t + off]; int i2 = ridx[t + off];
                if (v2 < rval[t] || (v2 == rval[t] && i2 < ridx[t])) {
                    rval[t] = v2; ridx[t] = i2;
                }
            }
            __syncthreads();
        }
        if (t == 0) g_find[n] = (float)ridx[0];
        __syncthreads();
    }
}

// ---------------------------------------------------------------------------
// Kernel 4: z_q with EXACT dmin (gather chosen code, fp32 dot), output
// transpose, fixed-point loss accumulation. Grid 1024, 256 threads.
// ---------------------------------------------------------------------------
__global__ __launch_bounds__(256)
void zq_kernel(const float* __restrict__ z,
               const float* __restrict__ noise,
               const float* __restrict__ cb,
               float* __restrict__ out,
               float* __restrict__ out_ind,
               float* __restrict__ out_loss) {
    __shared__ float zt[64][33];
    __shared__ float zq[32 * 65];
    __shared__ float sred[256];
    int t = threadIdx.x;
    int c = blockIdx.x;
    int b = c >> 5;
    int p = c & 31;
    int r0 = b * 1024 + p * 32;

    int row = t >> 3;
    int seg = t & 7;
    int n = r0 + row;

    // hoisted independent loads
    float4 n0 = *(const float4*)&noise[n * 64 + seg * 8];
    float4 n1 = *(const float4*)&noise[n * 64 + seg * 8 + 4];
    float mi = g_find[n];
    int ci = (int)mi;
    float y2c = g_y2[ci];
    float4 c0 = *(const float4*)&cb[ci * 64 + seg * 8];
    float4 c1 = *(const float4*)&cb[ci * 64 + seg * 8 + 4];

    // load z tile
    {
        const float* zb = z + (size_t)b * 65536 + p * 32;
        int w = t & 31, db = t >> 5;
        #pragma unroll
        for (int it = 0; it < 8; ++it) {
            int d = it * 8 + db;
            zt[d][w] = zb[d * 1024 + w];
        }
    }
    __syncthreads();

    float nv[8] = {n0.x, n0.y, n0.z, n0.w, n1.x, n1.y, n1.z, n1.w};
    float cv[8] = {c0.x, c0.y, c0.z, c0.w, c1.x, c1.y, c1.z, c1.w};
    float zv[8];
    #pragma unroll
    for (int i = 0; i < 8; ++i) zv[i] = zt[seg * 8 + i][row];

    float s = 0.f, xs = 0.f, ds = 0.f;
    #pragma unroll
    for (int i = 0; i < 8; ++i) {
        s += nv[i] * nv[i];
        xs += zv[i] * zv[i];
        ds += zv[i] * cv[i];
    }
    s  += __shfl_down_sync(0xffffffffu, s, 4, 8);
    xs += __shfl_down_sync(0xffffffffu, xs, 4, 8);
    ds += __shfl_down_sync(0xffffffffu, ds, 4, 8);
    s  += __shfl_down_sync(0xffffffffu, s, 2, 8);
    xs += __shfl_down_sync(0xffffffffu, xs, 2, 8);
    ds += __shfl_down_sync(0xffffffffu, ds, 2, 8);
    s  += __shfl_down_sync(0xffffffffu, s, 1, 8);
    xs += __shfl_down_sync(0xffffffffu, xs, 1, 8);
    ds += __shfl_down_sync(0xffffffffu, ds, 1, 8);
    float norm2 = __shfl_sync(0xffffffffu, s, 0, 8);
    float x2    = __shfl_sync(0xffffffffu, xs, 0, 8);
    float dot   = __shfl_sync(0xffffffffu, ds, 0, 8);

    if (seg == 0) out_ind[n] = mi;

    float dmin = x2 + y2c - 2.0f * dot;   // exact fp32 distance
    float scale = sqrtf(fmaxf(dmin, 0.f)) / fmaxf(sqrtf(norm2), 1e-9f);

    float part = 0.f;
    #pragma unroll
    for (int i = 0; i < 8; ++i) {
        float q = zv[i] + nv[i] * scale;
        part += q;
        zq[row * 65 + seg * 8 + i] = q;
    }
    sred[t] = part;
    __syncthreads();

    for (int off = 64; off > 0; off >>= 1) {
        if ((t & 127) < off) sred[t] += sred[t + off];
        __syncthreads();
    }
    if ((t & 127) == 0) {
        float sv = sred[t];
        unsigned long long q =
            (unsigned long long)__double2ll_rn((double)sv * (double)sv * 4194304.0);
        atomicAdd(&g_lacc, q);
    }

    {
        int dd = t >> 2;
        int rg = t & 3;
        float4 o0, o1;
        o0.x = zq[(rg * 8 + 0) * 65 + dd];
        o0.y = zq[(rg * 8 + 1) * 65 + dd];
        o0.z = zq[(rg * 8 + 2) * 65 + dd];
        o0.w = zq[(rg * 8 + 3) * 65 + dd];
        o1.x = zq[(rg * 8 + 4) * 65 + dd];
        o1.y = zq[(rg * 8 + 5) * 65 + dd];
        o1.z = zq[(rg * 8 + 6) * 65 + dd];
        o1.w = zq[(rg * 8 + 7) * 65 + dd];
        float* op = out + (size_t)b * 65536 + dd * 1024 + p * 32 + rg * 8;
        *(float4*)op = o0;
        *(float4*)(op + 4) = o1;
    }

    __syncthreads();
    if (t == 0) {
        __threadfence();
        int v = atomicAdd(&g_ctr, 1);
        if (v == (int)gridDim.x - 1) {
            unsigned long long tot = atomicAdd(&g_lacc, 0ull);
            *out_loss = (float)((double)tot * (1.0 / 4194304.0) * (1.0 / 33554432.0));
            g_lacc = 0ull;
            g_ctr = 0;
        }
    }
}

// ---------------------------------------------------------------------------
extern "C" void kernel_launch(void* const* d_in, const int* in_sizes, int n_in,
                              void* d_out, int out_size) {
    const float* z     = (const float*)d_in[0];
    const float* cb    = (const float*)d_in[1];
    const float* noise = (const float*)d_in[2];
    float* out      = (float*)d_out;
    float* out_loss = out + ZQ_ELEMS;
    float* out_ind  = out + ZQ_ELEMS + 1;

    cudaFuncSetAttribute(gemm_argmin_kernel,
                         cudaFuncAttributeMaxDynamicSharedMemorySize, GEMM_SMEM);

    bprep_kernel<<<128, 256>>>(cb);
    gemm_argmin_kernel<<<128, 512, GEMM_SMEM>>>(z);
    fix_kernel<<<256, 256>>>(z, cb);
    zq_kernel<<<1024, 256>>>(z, noise, cb, out, out_ind, out_loss);
}

// round 10
// speedup vs baseline: 14.4671x; 14.4671x over previous
#include <cuda_runtime.h>
#include <math.h>
#include <stdint.h>

// Problem constants
#define NROWS 32768   // B*H*W
#define DDIM  64
#define MCODE 1024
#define HWSZ  1024
#define ZQ_ELEMS 2097152

// Static device scratch
__device__ float g_b1[2 * NROWS];        // per code-half: best approx key
__device__ float g_b2[2 * NROWS];        // per code-half: 2nd-best approx key
__device__ float g_i1[2 * NROWS];        // per code-half: best idx (float)
__device__ float g_x2[NROWS];            // per-row squared norm
__device__ float g_find[NROWS];          // final argmin idx (float)
__device__ float g_y2[MCODE];
__device__ int   g_y2max_i = 0;          // max y2 as int bits (positive floats)
__device__ unsigned long long g_lacc = 0ull;  // fixed-point sum of s^2 (scale 2^22)
__device__ int   g_ctr = 0;              // zq completion counter (self-resetting)
__device__ int   g_wcount = 0;           // ambiguous-row worklist count (self-resetting)
__device__ int   g_wlist[NROWS];         // ambiguous-row worklist
// Codebook hi-tf32, fragment order: [chunk(16)][s(8)][ci(64)][t(4)] uint2{h0,h1}
__device__ uint2 g_bh[16 * 2048];
// Transposed fp32 codebook: cbT[k][c] (coalesced exact-rescan reads)
__device__ float4 g_cbT4[64 * 256];

// ---------------------------------------------------------------------------
// helpers
// ---------------------------------------------------------------------------
__device__ __forceinline__ uint32_t f2tf32(float a) {
    uint32_t r; asm("cvt.rna.tf32.f32 %0, %1;" : "=r"(r) : "f"(a)); return r;
}
__device__ __forceinline__ uint32_t smem_u32(const void* p) {
    uint32_t a;
    asm("{ .reg .u64 t; cvta.to.shared.u64 t, %1; cvt.u32.u64 %0, t; }"
        : "=r"(a) : "l"(p));
    return a;
}
__device__ __forceinline__ void bulk_g2s(uint32_t dst, const void* src,
                                         uint32_t bytes, uint32_t mbar) {
    asm volatile(
        "cp.async.bulk.shared::cta.global.mbarrier::complete_tx::bytes [%0], [%1], %2, [%3];"
        :: "r"(dst), "l"(src), "r"(bytes), "r"(mbar) : "memory");
}
__device__ __forceinline__ void mbar_init(uint32_t mbar, uint32_t cnt) {
    asm volatile("mbarrier.init.shared.b64 [%0], %1;" :: "r"(mbar), "r"(cnt) : "memory");
}
__device__ __forceinline__ void mbar_expect_tx(uint32_t mbar, uint32_t bytes) {
    asm volatile("mbarrier.arrive.expect_tx.shared.b64 _, [%0], %1;"
                 :: "r"(mbar), "r"(bytes) : "memory");
}
__device__ __forceinline__ void mbar_wait(uint32_t mbar, uint32_t parity) {
    uint32_t done;
    asm volatile(
        "{\n\t.reg .pred p;\n\t"
        "mbarrier.try_wait.parity.acquire.cta.shared::cta.b64 p, [%1], %2;\n\t"
        "selp.b32 %0, 1, 0, p;\n\t}"
        : "=r"(done) : "r"(mbar), "r"(parity) : "memory");
    while (!done) {
        asm volatile(
            "{\n\t.reg .pred p;\n\t"
            "mbarrier.try_wait.parity.acquire.cta.shared::cta.b64 p, [%1], %2, 0x989680;\n\t"
            "selp.b32 %0, 1, 0, p;\n\t}"
            : "=r"(done) : "r"(mbar), "r"(parity) : "memory");
    }
}
// D = A(16x8) * B(8x8) + C, tf32, fp32 accum
__device__ __forceinline__ void mma16n8k8(float* c, uint32_t a0, uint32_t a1,
                                          uint32_t a2, uint32_t a3,
                                          uint32_t b0, uint32_t b1) {
    asm volatile(
        "mma.sync.aligned.m16n8k8.row.col.f32.tf32.tf32.f32 "
        "{%0,%1,%2,%3}, {%4,%5,%6,%7}, {%8,%9}, {%0,%1,%2,%3};"
        : "+f"(c[0]), "+f"(c[1]), "+f"(c[2]), "+f"(c[3])
        : "r"(a0), "r"(a1), "r"(a2), "r"(a3), "r"(b0), "r"(b1));
}

// ---------------------------------------------------------------------------
// Kernel 1: pack codebook (hi tf32) + transposed fp32 copy + y2 + y2max.
// ---------------------------------------------------------------------------
__global__ void bprep_kernel(const float* __restrict__ cb) {
    int g = blockIdx.x * 256 + threadIdx.x;
    int c = g >> 5, s = (g >> 2) & 7, t = g & 3;
    float v0 = cb[c * DDIM + s * 8 + t];
    float v1 = cb[c * DDIM + s * 8 + t + 4];
    uint32_t h0 = f2tf32(v0), h1 = f2tf32(v1);
    int chunk = c >> 6, ci = c & 63;
    g_bh[chunk * 2048 + s * 256 + ci * 4 + t] = make_uint2(h0, h1);
    // transposed copy for the exact-rescan path
    float* cbT = (float*)g_cbT4;
    cbT[(s * 8 + t) * 1024 + c] = v0;
    cbT[(s * 8 + t + 4) * 1024 + c] = v1;
    float y = v0 * v0 + v1 * v1;
    #pragma unroll
    for (int d = 16; d > 0; d >>= 1)
        y += __shfl_xor_sync(0xffffffffu, y, d);
    if ((threadIdx.x & 31) == 0) {
        g_y2[c] = y;
        atomicMax(&g_y2max_i, __float_as_int(y));
    }
}

// ---------------------------------------------------------------------------
// Kernel 2: 1-pass TF32 mma.sync GEMM + best/2nd-best argmin tracking.
// (UNCHANGED from R9.)
// ---------------------------------------------------------------------------
#define SM_MB   0
#define SM_Y2   128
#define SM_A    2176
#define SM_B    133248
#define GEMM_SMEM 166016

__global__ __launch_bounds__(512, 1)
void gemm_argmin_kernel(const float* __restrict__ z) {
    extern __shared__ char sm[];
    uint32_t sb = smem_u32(sm);
    uint2* A2 = (uint2*)(sm + SM_A);
    const float* y2s = (const float*)(sm + SM_Y2);
    int tid = threadIdx.x;
    int wid = tid >> 5, lane = tid & 31;
    int g = lane >> 2, tt = lane & 3;
    int half = blockIdx.x & 1;
    int rb = blockIdx.x >> 1;            // 0..63
    int r0 = rb * 512;
    int w32 = wid * 32;
    const uint2* bsrc = g_bh + half * 16384;

    if (tid == 0) {
        mbar_init(sb + SM_MB + 0, 1);
        mbar_init(sb + SM_MB + 8, 1);
    }
    __syncthreads();

    if (tid == 0) {
        mbar_expect_tx(sb + SM_MB + 0, 16384);
        bulk_g2s(sb + SM_B, bsrc, 16384, sb + SM_MB + 0);
        mbar_expect_tx(sb + SM_MB + 8, 16384);
        bulk_g2s(sb + SM_B + 16384, bsrc + 2048, 16384, sb + SM_MB + 8);
    }

    // A prep: z -> hi-tf32 pairs + per-row x2 (half 0 writes)
    {
        const float* zb = z + (size_t)(rb >> 1) * (DDIM * HWSZ) + (rb & 1) * 512;
        int roff = lane >> 2, tp = lane & 3;
        #pragma unroll
        for (int p = 0; p < 4; ++p) {
            int r = p * 128 + wid * 8 + roff;
            float sq = 0.f;
            #pragma unroll
            for (int s = 0; s < 8; ++s) {
                float v0 = zb[(s * 8 + tp) * HWSZ + r];
                float v1 = zb[(s * 8 + tp + 4) * HWSZ + r];
                sq += v0 * v0 + v1 * v1;
                A2[(s * 512 + r) * 4 + tp] = make_uint2(f2tf32(v0), f2tf32(v1));
            }
            sq += __shfl_xor_sync(0xffffffffu, sq, 1);
            sq += __shfl_xor_sync(0xffffffffu, sq, 2);
            if (tp == 0 && half == 0) g_x2[r0 + r] = sq;
        }
    }
    for (int i = tid; i < 512; i += 512)
        ((float*)(sm + SM_Y2))[i] = g_y2[half * 512 + i];
    __syncthreads();

    float best[4], bst2[4];
    int   bidx[4];
    #pragma unroll
    for (int i = 0; i < 4; ++i) { best[i] = 3.4028235e38f; bst2[i] = 3.4028235e38f; bidx[i] = 0; }

    for (int ch = 0; ch < 8; ++ch) {
        int buf = ch & 1;
        mbar_wait(sb + SM_MB + buf * 8, (ch >> 1) & 1);
        const uint2* Bb = (const uint2*)(sm + SM_B + buf * 16384);

        float acc[2][8][4];
        #pragma unroll
        for (int m = 0; m < 2; ++m)
            #pragma unroll
            for (int j = 0; j < 8; ++j)
                #pragma unroll
                for (int e = 0; e < 4; ++e) acc[m][j][e] = 0.f;

        #pragma unroll
        for (int s = 0; s < 8; ++s) {
            uint2 a0 = A2[(s * 512 + w32 + g) * 4 + tt];
            uint2 a1 = A2[(s * 512 + w32 + 8 + g) * 4 + tt];
            uint2 a2 = A2[(s * 512 + w32 + 16 + g) * 4 + tt];
            uint2 a3 = A2[(s * 512 + w32 + 24 + g) * 4 + tt];
            #pragma unroll
            for (int j = 0; j < 8; ++j) {
                uint2 bq = Bb[s * 256 + (j * 8 + g) * 4 + tt];
                mma16n8k8(acc[0][j], a0.x, a1.x, a0.y, a1.y, bq.x, bq.y);
                mma16n8k8(acc[1][j], a2.x, a3.x, a2.y, a3.y, bq.x, bq.y);
            }
        }

        #pragma unroll
        for (int j = 0; j < 8; ++j) {
            int cl = ch * 64 + j * 8 + 2 * tt;
            float2 y = ((const float2*)y2s)[cl >> 1];
            #pragma unroll
            for (int m = 0; m < 2; ++m) {
                float k0 = fmaf(acc[m][j][0], -2.0f, y.x);
                float k1 = fmaf(acc[m][j][1], -2.0f, y.y);
                float k2 = fmaf(acc[m][j][2], -2.0f, y.x);
                float k3 = fmaf(acc[m][j][3], -2.0f, y.y);
                int s0 = m * 2, s1 = m * 2 + 1;
                if (k0 < best[s0]) { bst2[s0] = best[s0]; best[s0] = k0; bidx[s0] = cl; }
                else if (k0 < bst2[s0]) bst2[s0] = k0;
                if (k1 < best[s0]) { bst2[s0] = best[s0]; best[s0] = k1; bidx[s0] = cl + 1; }
                else if (k1 < bst2[s0]) bst2[s0] = k1;
                if (k2 < best[s1]) { bst2[s1] = best[s1]; best[s1] = k2; bidx[s1] = cl; }
                else if (k2 < bst2[s1]) bst2[s1] = k2;
                if (k3 < best[s1]) { bst2[s1] = best[s1]; best[s1] = k3; bidx[s1] = cl + 1; }
                else if (k3 < bst2[s1]) bst2[s1] = k3;
            }
        }

        __syncthreads();
        if (ch + 2 < 8 && tid == 0) {
            mbar_expect_tx(sb + SM_MB + buf * 8, 16384);
            bulk_g2s(sb + SM_B + buf * 16384, bsrc + (ch + 2) * 2048, 16384,
                     sb + SM_MB + buf * 8);
        }
    }

    #pragma unroll
    for (int m = 0; m < 4; ++m) {
        float b1 = best[m], b2 = bst2[m];
        int i1 = bidx[m];
        #pragma unroll
        for (int d = 1; d < 4; d <<= 1) {
            float ob1 = __shfl_xor_sync(0xffffffffu, b1, d);
            int   oi1 = __shfl_xor_sync(0xffffffffu, i1, d);
            float ob2 = __shfl_xor_sync(0xffffffffu, b2, d);
            float nb2 = fminf(fmaxf(b1, ob1), fminf(b2, ob2));
            if (ob1 < b1 || (ob1 == b1 && oi1 < i1)) { b1 = ob1; i1 = oi1; }
            b2 = nb2;
        }
        if (tt == 0) {
            int row = r0 + w32 + (m >> 1) * 16 + (m & 1) * 8 + g;
            g_b1[half * NROWS + row] = b1;
            g_b2[half * NROWS + row] = b2;
            g_i1[half * NROWS + row] = (float)(half * 512 + i1);
        }
    }
}

// ---------------------------------------------------------------------------
// Kernel 3: triage — merge halves, margin test; confident rows resolved,
// ambiguous rows appended to a global worklist. Grid 128 x 256 (1 row/thr).
// ---------------------------------------------------------------------------
__global__ __launch_bounds__(256)
void triage_kernel() {
    int n = blockIdx.x * 256 + threadIdx.x;
    float b10 = g_b1[n],         b11 = g_b1[NROWS + n];
    float b20 = g_b2[n],         b21 = g_b2[NROWS + n];
    float i10 = g_i1[n],         i11 = g_i1[NROWS + n];
    float fb, fi, fs;
    if (b11 < b10) { fb = b11; fi = i11; fs = fminf(b10, b21); }
    else           { fb = b10; fi = i10; fs = fminf(b11, b20); }
    float y2max = __int_as_float(g_y2max_i);
    float eps = 0.006f * sqrtf(g_x2[n] * y2max) + 1e-3f;
    if (fs - fb > eps) {
        g_find[n] = fi;
    } else {
        int sl = atomicAdd(&g_wcount, 1);
        g_wlist[sl] = n;
    }
}

// ---------------------------------------------------------------------------
// Kernel 4: exact fp32 rescan for ambiguous rows. Batch of 4 rows per pass;
// coalesced transposed-codebook reads (1 LDG.128 feeds 16 FMAs).
// Grid 512 x 256; CTA j handles batches j, j+512, ...
// ---------------------------------------------------------------------------
__global__ __launch_bounds__(256)
void fix_kernel(const float* __restrict__ z) {
    __shared__ float zsm[4][64];
    __shared__ int   rowid[4];
    __shared__ float rv[256];
    __shared__ int   ri[256];
    int t = threadIdx.x;
    int cnt = g_wcount;

    for (int base = blockIdx.x * 4; base < cnt; base += 2048) {
        if (t < 4)
            rowid[t] = (base + t < cnt) ? g_wlist[base + t] : -1;
        __syncthreads();
        {
            int r = t >> 6, k = t & 63;
            int n = rowid[r];
            zsm[r][k] = (n >= 0)
                ? z[(size_t)(n >> 10) * 65536 + k * 1024 + (n & 1023)] : 0.f;
        }
        __syncthreads();

        // thread t owns codes 4t..4t+3; accumulate 4 rows x 4 codes
        float d[4][4];
        #pragma unroll
        for (int r = 0; r < 4; ++r)
            #pragma unroll
            for (int j = 0; j < 4; ++j) d[r][j] = 0.f;
        #pragma unroll 8
        for (int k = 0; k < 64; ++k) {
            float4 cv = g_cbT4[k * 256 + t];
            #pragma unroll
            for (int r = 0; r < 4; ++r) {
                float zk = zsm[r][k];
                d[r][0] = fmaf(zk, cv.x, d[r][0]);
                d[r][1] = fmaf(zk, cv.y, d[r][1]);
                d[r][2] = fmaf(zk, cv.z, d[r][2]);
                d[r][3] = fmaf(zk, cv.w, d[r][3]);
            }
        }
        float2 ya = ((const float2*)g_y2)[2 * t];
        float2 yb = ((const float2*)g_y2)[2 * t + 1];
        float yj[4] = {ya.x, ya.y, yb.x, yb.y};

        #pragma unroll
        for (int r = 0; r < 4; ++r) {
            float bv = 3.4028235e38f;
            int bi = 0;
            #pragma unroll
            for (int j = 0; j < 4; ++j) {
                float key = fmaf(d[r][j], -2.0f, yj[j]);
                if (key < bv) { bv = key; bi = 4 * t + j; }   // ascending j
            }
            rv[t] = bv; ri[t] = bi;
            __syncthreads();
            for (int off = 128; off > 0; off >>= 1) {
                if (t < off) {
                    float v2 = rv[t + off]; int i2 = ri[t + off];
                    if (v2 < rv[t] || (v2 == rv[t] && i2 < ri[t])) {
                        rv[t] = v2; ri[t] = i2;
                    }
                }
                __syncthreads();
            }
            if (t == 0 && rowid[r] >= 0) g_find[rowid[r]] = (float)ri[0];
            __syncthreads();
        }
    }
}

// ---------------------------------------------------------------------------
// Kernel 5: z_q with EXACT dmin (gather chosen code), output transpose,
// fixed-point loss. Grid 1024 x 256. Last CTA finalizes loss + resets.
// ---------------------------------------------------------------------------
__global__ __launch_bounds__(256)
void zq_kernel(const float* __restrict__ z,
               const float* __restrict__ noise,
               const float* __restrict__ cb,
               float* __restrict__ out,
               float* __restrict__ out_ind,
               float* __restrict__ out_loss) {
    __shared__ float zt[64][33];
    __shared__ float zq[32 * 65];
    __shared__ float sred[256];
    int t = threadIdx.x;
    int c = blockIdx.x;
    int b = c >> 5;
    int p = c & 31;
    int r0 = b * 1024 + p * 32;

    int row = t >> 3;
    int seg = t & 7;
    int n = r0 + row;

    float4 n0 = *(const float4*)&noise[n * 64 + seg * 8];
    float4 n1 = *(const float4*)&noise[n * 64 + seg * 8 + 4];
    float mi = g_find[n];
    int ci = (int)mi;
    float y2c = g_y2[ci];
    float4 c0 = *(const float4*)&cb[ci * 64 + seg * 8];
    float4 c1 = *(const float4*)&cb[ci * 64 + seg * 8 + 4];

    {
        const float* zb = z + (size_t)b * 65536 + p * 32;
        int w = t & 31, db = t >> 5;
        #pragma unroll
        for (int it = 0; it < 8; ++it) {
            int d = it * 8 + db;
            zt[d][w] = zb[d * 1024 + w];
        }
    }
    __syncthreads();

    float nv[8] = {n0.x, n0.y, n0.z, n0.w, n1.x, n1.y, n1.z, n1.w};
    float cv[8] = {c0.x, c0.y, c0.z, c0.w, c1.x, c1.y, c1.z, c1.w};
    float zv[8];
    #pragma unroll
    for (int i = 0; i < 8; ++i) zv[i] = zt[seg * 8 + i][row];

    float s = 0.f, xs = 0.f, ds = 0.f;
    #pragma unroll
    for (int i = 0; i < 8; ++i) {
        s += nv[i] * nv[i];
        xs += zv[i] * zv[i];
        ds += zv[i] * cv[i];
    }
    s  += __shfl_down_sync(0xffffffffu, s, 4, 8);
    xs += __shfl_down_sync(0xffffffffu, xs, 4, 8);
    ds += __shfl_down_sync(0xffffffffu, ds, 4, 8);
    s  += __shfl_down_sync(0xffffffffu, s, 2, 8);
    xs += __shfl_down_sync(0xffffffffu, xs, 2, 8);
    ds += __shfl_down_sync(0xffffffffu, ds, 2, 8);
    s  += __shfl_down_sync(0xffffffffu, s, 1, 8);
    xs += __shfl_down_sync(0xffffffffu, xs, 1, 8);
    ds += __shfl_down_sync(0xffffffffu, ds, 1, 8);
    float norm2 = __shfl_sync(0xffffffffu, s, 0, 8);
    float x2    = __shfl_sync(0xffffffffu, xs, 0, 8);
    float dot   = __shfl_sync(0xffffffffu, ds, 0, 8);

    if (seg == 0) out_ind[n] = mi;

    float dmin = x2 + y2c - 2.0f * dot;
    float scale = sqrtf(fmaxf(dmin, 0.f)) / fmaxf(sqrtf(norm2), 1e-9f);

    float part = 0.f;
    #pragma unroll
    for (int i = 0; i < 8; ++i) {
        float q = zv[i] + nv[i] * scale;
        part += q;
        zq[row * 65 + seg * 8 + i] = q;
    }
    sred[t] = part;
    __syncthreads();

    for (int off = 64; off > 0; off >>= 1) {
        if ((t & 127) < off) sred[t] += sred[t + off];
        __syncthreads();
    }
    if ((t & 127) == 0) {
        float sv = sred[t];
        unsigned long long q =
            (unsigned long long)__double2ll_rn((double)sv * (double)sv * 4194304.0);
        atomicAdd(&g_lacc, q);
    }

    {
        int dd = t >> 2;
        int rg = t & 3;
        float4 o0, o1;
        o0.x = zq[(rg * 8 + 0) * 65 + dd];
        o0.y = zq[(rg * 8 + 1) * 65 + dd];
        o0.z = zq[(rg * 8 + 2) * 65 + dd];
        o0.w = zq[(rg * 8 + 3) * 65 + dd];
        o1.x = zq[(rg * 8 + 4) * 65 + dd];
        o1.y = zq[(rg * 8 + 5) * 65 + dd];
        o1.z = zq[(rg * 8 + 6) * 65 + dd];
        o1.w = zq[(rg * 8 + 7) * 65 + dd];
        float* op = out + (size_t)b * 65536 + dd * 1024 + p * 32 + rg * 8;
        *(float4*)op = o0;
        *(float4*)(op + 4) = o1;
    }

    __syncthreads();
    if (t == 0) {
        __threadfence();
        int v = atomicAdd(&g_ctr, 1);
        if (v == (int)gridDim.x - 1) {
            unsigned long long tot = atomicAdd(&g_lacc, 0ull);
            *out_loss = (float)((double)tot * (1.0 / 4194304.0) * (1.0 / 33554432.0));
            g_lacc = 0ull;
            g_ctr = 0;
            g_wcount = 0;   // reset worklist for next graph replay
        }
    }
}

// ---------------------------------------------------------------------------
extern "C" void kernel_launch(void* const* d_in, const int* in_sizes, int n_in,
                              void* d_out, int out_size) {
    const float* z     = (const float*)d_in[0];
    const float* cb    = (const float*)d_in[1];
    const float* noise = (const float*)d_in[2];
    float* out      = (float*)d_out;
    float* out_loss = out + ZQ_ELEMS;
    float* out_ind  = out + ZQ_ELEMS + 1;

    cudaFuncSetAttribute(gemm_argmin_kernel,
                         cudaFuncAttributeMaxDynamicSharedMemorySize, GEMM_SMEM);

    bprep_kernel<<<128, 256>>>(cb);
    gemm_argmin_kernel<<<128, 512, GEMM_SMEM>>>(z);
    triage_kernel<<<128, 256>>>();
    fix_kernel<<<512, 256>>>(z);
    zq_kernel<<<1024, 256>>>(z, noise, cb, out, out_ind, out_loss);
}

// round 11
// speedup vs baseline: 15.7618x; 1.0895x over previous
#include <cuda_runtime.h>
#include <math.h>
#include <stdint.h>

// Problem constants
#define NROWS 32768   // B*H*W
#define DDIM  64
#define MCODE 1024
#define HWSZ  1024
#define ZQ_ELEMS 2097152

// Static device scratch
__device__ float g_b1[2 * NROWS];        // per code-half: best approx key
__device__ float g_b2[2 * NROWS];        // per code-half: 2nd-best approx key
__device__ float g_i1[2 * NROWS];        // per code-half: best idx (float)
__device__ float g_x2[NROWS];            // per-row squared norm
__device__ float g_find[NROWS];          // final idx (>=0) or -1 => see g_packres
__device__ unsigned long long g_packres[NROWS];  // packed (sortable key | idx)
__device__ float g_zf[NROWS * DDIM];     // compact fp32 rows (written by gemm1)
__device__ float g_y2[MCODE];
__device__ int   g_y2max_i = 0;
__device__ unsigned long long g_lacc = 0ull;  // fixed-point sum of s^2 (scale 2^22)
__device__ int   g_ctr = 0;              // zq completion counter (self-resetting)
__device__ int   g_wcount = 0;           // ambiguous worklist count (self-resetting)
__device__ int   g_wlist[NROWS];
// Codebook hi-tf32 (gemm1): [chunk16][s8][ci64][t4] uint2{h0,h1}
__device__ uint2 g_bh[16 * 2048];
// Codebook hi/lo tf32 (fix): [chunk16][s8][ci64][t4] uint4{h0,h1,l0,l1}
__device__ uint4 g_bpack4[16 * 2048];

// ---------------------------------------------------------------------------
// helpers
// ---------------------------------------------------------------------------
__device__ __forceinline__ uint32_t f2tf32(float a) {
    uint32_t r; asm("cvt.rna.tf32.f32 %0, %1;" : "=r"(r) : "f"(a)); return r;
}
__device__ __forceinline__ uint32_t smem_u32(const void* p) {
    uint32_t a;
    asm("{ .reg .u64 t; cvta.to.shared.u64 t, %1; cvt.u32.u64 %0, t; }"
        : "=r"(a) : "l"(p));
    return a;
}
__device__ __forceinline__ void bulk_g2s(uint32_t dst, const void* src,
                                         uint32_t bytes, uint32_t mbar) {
    asm volatile(
        "cp.async.bulk.shared::cta.global.mbarrier::complete_tx::bytes [%0], [%1], %2, [%3];"
        :: "r"(dst), "l"(src), "r"(bytes), "r"(mbar) : "memory");
}
__device__ __forceinline__ void mbar_init(uint32_t mbar, uint32_t cnt) {
    asm volatile("mbarrier.init.shared.b64 [%0], %1;" :: "r"(mbar), "r"(cnt) : "memory");
}
__device__ __forceinline__ void mbar_expect_tx(uint32_t mbar, uint32_t bytes) {
    asm volatile("mbarrier.arrive.expect_tx.shared.b64 _, [%0], %1;"
                 :: "r"(mbar), "r"(bytes) : "memory");
}
__device__ __forceinline__ void mbar_wait(uint32_t mbar, uint32_t parity) {
    uint32_t done;
    asm volatile(
        "{\n\t.reg .pred p;\n\t"
        "mbarrier.try_wait.parity.acquire.cta.shared::cta.b64 p, [%1], %2;\n\t"
        "selp.b32 %0, 1, 0, p;\n\t}"
        : "=r"(done) : "r"(mbar), "r"(parity) : "memory");
    while (!done) {
        asm volatile(
            "{\n\t.reg .pred p;\n\t"
            "mbarrier.try_wait.parity.acquire.cta.shared::cta.b64 p, [%1], %2, 0x989680;\n\t"
            "selp.b32 %0, 1, 0, p;\n\t}"
            : "=r"(done) : "r"(mbar), "r"(parity) : "memory");
    }
}
__device__ __forceinline__ void mma16n8k8(float* c, uint32_t a0, uint32_t a1,
                                          uint32_t a2, uint32_t a3,
                                          uint32_t b0, uint32_t b1) {
    asm volatile(
        "mma.sync.aligned.m16n8k8.row.col.f32.tf32.tf32.f32 "
        "{%0,%1,%2,%3}, {%4,%5,%6,%7}, {%8,%9}, {%0,%1,%2,%3};"
        : "+f"(c[0]), "+f"(c[1]), "+f"(c[2]), "+f"(c[3])
        : "r"(a0), "r"(a1), "r"(a2), "r"(a3), "r"(b0), "r"(b1));
}
#define CP_ASYNC16(dst, src) \
    asm volatile("cp.async.cg.shared.global [%0], [%1], 16;" :: "r"(dst), "l"(src))
#define CP_COMMIT() asm volatile("cp.async.commit_group;" ::: "memory")
#define CP_WAIT(n)  asm volatile("cp.async.wait_group %0;" :: "n"(n) : "memory")

// float key -> order-preserving uint32 (handles negatives)
__device__ __forceinline__ unsigned long long pack_key(float k, int idx) {
    uint32_t u = __float_as_uint(k);
    u = (u & 0x80000000u) ? ~u : (u | 0x80000000u);
    return ((unsigned long long)u << 32) | (uint32_t)idx;
}

// ---------------------------------------------------------------------------
// Kernel 1: pack codebook (hi uint2 for gemm1; hi/lo uint4 for fix) + y2.
// ---------------------------------------------------------------------------
__global__ void bprep_kernel(const float* __restrict__ cb) {
    int g = blockIdx.x * 256 + threadIdx.x;
    int c = g >> 5, s = (g >> 2) & 7, t = g & 3;
    float v0 = cb[c * DDIM + s * 8 + t];
    float v1 = cb[c * DDIM + s * 8 + t + 4];
    uint32_t h0 = f2tf32(v0), h1 = f2tf32(v1);
    uint32_t l0 = f2tf32(v0 - __uint_as_float(h0));
    uint32_t l1 = f2tf32(v1 - __uint_as_float(h1));
    int chunk = c >> 6, ci = c & 63;
    int off = chunk * 2048 + s * 256 + ci * 4 + t;
    g_bh[off] = make_uint2(h0, h1);
    g_bpack4[off] = make_uint4(h0, h1, l0, l1);
    float y = v0 * v0 + v1 * v1;
    #pragma unroll
    for (int d = 16; d > 0; d >>= 1)
        y += __shfl_xor_sync(0xffffffffu, y, d);
    if ((threadIdx.x & 31) == 0) {
        g_y2[c] = y;
        atomicMax(&g_y2max_i, __float_as_int(y));
    }
}

// ---------------------------------------------------------------------------
// Kernel 2: 1-pass TF32 gemm + best/2nd-best. Also streams compact zf rows.
// ---------------------------------------------------------------------------
#define SM_MB   0
#define SM_Y2   128
#define SM_A    2176
#define SM_B    133248
#define GEMM_SMEM 166016

__global__ __launch_bounds__(512, 1)
void gemm_argmin_kernel(const float* __restrict__ z) {
    extern __shared__ char sm[];
    uint32_t sb = smem_u32(sm);
    uint2* A2 = (uint2*)(sm + SM_A);
    const float* y2s = (const float*)(sm + SM_Y2);
    int tid = threadIdx.x;
    int wid = tid >> 5, lane = tid & 31;
    int g = lane >> 2, tt = lane & 3;
    int half = blockIdx.x & 1;
    int rb = blockIdx.x >> 1;
    int r0 = rb * 512;
    int w32 = wid * 32;
    const uint2* bsrc = g_bh + half * 16384;

    if (tid == 0) {
        mbar_init(sb + SM_MB + 0, 1);
        mbar_init(sb + SM_MB + 8, 1);
    }
    __syncthreads();

    if (tid == 0) {
        mbar_expect_tx(sb + SM_MB + 0, 16384);
        bulk_g2s(sb + SM_B, bsrc, 16384, sb + SM_MB + 0);
        mbar_expect_tx(sb + SM_MB + 8, 16384);
        bulk_g2s(sb + SM_B + 16384, bsrc + 2048, 16384, sb + SM_MB + 8);
    }

    // A prep: z -> hi tf32 pairs + x2 + compact zf (half 0 writes)
    {
        const float* zb = z + (size_t)(rb >> 1) * (DDIM * HWSZ) + (rb & 1) * 512;
        int roff = lane >> 2, tp = lane & 3;
        #pragma unroll
        for (int p = 0; p < 4; ++p) {
            int r = p * 128 + wid * 8 + roff;
            float sq = 0.f;
            #pragma unroll
            for (int s = 0; s < 8; ++s) {
                float v0 = zb[(s * 8 + tp) * HWSZ + r];
                float v1 = zb[(s * 8 + tp + 4) * HWSZ + r];
                sq += v0 * v0 + v1 * v1;
                A2[(s * 512 + r) * 4 + tp] = make_uint2(f2tf32(v0), f2tf32(v1));
                if (half == 0) {
                    g_zf[(r0 + r) * 64 + s * 8 + tp] = v0;
                    g_zf[(r0 + r) * 64 + s * 8 + tp + 4] = v1;
                }
            }
            sq += __shfl_xor_sync(0xffffffffu, sq, 1);
            sq += __shfl_xor_sync(0xffffffffu, sq, 2);
            if (tp == 0 && half == 0) g_x2[r0 + r] = sq;
        }
    }
    for (int i = tid; i < 512; i += 512)
        ((float*)(sm + SM_Y2))[i] = g_y2[half * 512 + i];
    __syncthreads();

    float best[4], bst2[4];
    int   bidx[4];
    #pragma unroll
    for (int i = 0; i < 4; ++i) { best[i] = 3.4028235e38f; bst2[i] = 3.4028235e38f; bidx[i] = 0; }

    for (int ch = 0; ch < 8; ++ch) {
        int buf = ch & 1;
        mbar_wait(sb + SM_MB + buf * 8, (ch >> 1) & 1);
        const uint2* Bb = (const uint2*)(sm + SM_B + buf * 16384);

        float acc[2][8][4];
        #pragma unroll
        for (int m = 0; m < 2; ++m)
            #pragma unroll
            for (int j = 0; j < 8; ++j)
                #pragma unroll
                for (int e = 0; e < 4; ++e) acc[m][j][e] = 0.f;

        #pragma unroll
        for (int s = 0; s < 8; ++s) {
            uint2 a0 = A2[(s * 512 + w32 + g) * 4 + tt];
            uint2 a1 = A2[(s * 512 + w32 + 8 + g) * 4 + tt];
            uint2 a2 = A2[(s * 512 + w32 + 16 + g) * 4 + tt];
            uint2 a3 = A2[(s * 512 + w32 + 24 + g) * 4 + tt];
            #pragma unroll
            for (int j = 0; j < 8; ++j) {
                uint2 bq = Bb[s * 256 + (j * 8 + g) * 4 + tt];
                mma16n8k8(acc[0][j], a0.x, a1.x, a0.y, a1.y, bq.x, bq.y);
                mma16n8k8(acc[1][j], a2.x, a3.x, a2.y, a3.y, bq.x, bq.y);
            }
        }

        #pragma unroll
        for (int j = 0; j < 8; ++j) {
            int cl = ch * 64 + j * 8 + 2 * tt;
            float2 y = ((const float2*)y2s)[cl >> 1];
            #pragma unroll
            for (int m = 0; m < 2; ++m) {
                float k0 = fmaf(acc[m][j][0], -2.0f, y.x);
                float k1 = fmaf(acc[m][j][1], -2.0f, y.y);
                float k2 = fmaf(acc[m][j][2], -2.0f, y.x);
                float k3 = fmaf(acc[m][j][3], -2.0f, y.y);
                int s0 = m * 2, s1 = m * 2 + 1;
                if (k0 < best[s0]) { bst2[s0] = best[s0]; best[s0] = k0; bidx[s0] = cl; }
                else if (k0 < bst2[s0]) bst2[s0] = k0;
                if (k1 < best[s0]) { bst2[s0] = best[s0]; best[s0] = k1; bidx[s0] = cl + 1; }
                else if (k1 < bst2[s0]) bst2[s0] = k1;
                if (k2 < best[s1]) { bst2[s1] = best[s1]; best[s1] = k2; bidx[s1] = cl; }
                else if (k2 < bst2[s1]) bst2[s1] = k2;
                if (k3 < best[s1]) { bst2[s1] = best[s1]; best[s1] = k3; bidx[s1] = cl + 1; }
                else if (k3 < bst2[s1]) bst2[s1] = k3;
            }
        }

        __syncthreads();
        if (ch + 2 < 8 && tid == 0) {
            mbar_expect_tx(sb + SM_MB + buf * 8, 16384);
            bulk_g2s(sb + SM_B + buf * 16384, bsrc + (ch + 2) * 2048, 16384,
                     sb + SM_MB + buf * 8);
        }
    }

    #pragma unroll
    for (int m = 0; m < 4; ++m) {
        float b1 = best[m], b2 = bst2[m];
        int i1 = bidx[m];
        #pragma unroll
        for (int d = 1; d < 4; d <<= 1) {
            float ob1 = __shfl_xor_sync(0xffffffffu, b1, d);
            int   oi1 = __shfl_xor_sync(0xffffffffu, i1, d);
            float ob2 = __shfl_xor_sync(0xffffffffu, b2, d);
            float nb2 = fminf(fmaxf(b1, ob1), fminf(b2, ob2));
            if (ob1 < b1 || (ob1 == b1 && oi1 < i1)) { b1 = ob1; i1 = oi1; }
            b2 = nb2;
        }
        if (tt == 0) {
            int row = r0 + w32 + (m >> 1) * 16 + (m & 1) * 8 + g;
            g_b1[half * NROWS + row] = b1;
            g_b2[half * NROWS + row] = b2;
            g_i1[half * NROWS + row] = (float)(half * 512 + i1);
        }
    }
}

// ---------------------------------------------------------------------------
// Kernel 3: triage. Confident -> g_find; ambiguous -> worklist + init packres.
// ---------------------------------------------------------------------------
__global__ __launch_bounds__(256)
void triage_kernel() {
    int n = blockIdx.x * 256 + threadIdx.x;
    float b10 = g_b1[n],         b11 = g_b1[NROWS + n];
    float b20 = g_b2[n],         b21 = g_b2[NROWS + n];
    float i10 = g_i1[n],         i11 = g_i1[NROWS + n];
    float fb, fi, fs;
    if (b11 < b10) { fb = b11; fi = i11; fs = fminf(b10, b21); }
    else           { fb = b10; fi = i10; fs = fminf(b11, b20); }
    float y2max = __int_as_float(g_y2max_i);
    float eps = 0.006f * sqrtf(g_x2[n] * y2max) + 1e-3f;
    if (fs - fb > eps) {
        g_find[n] = fi;
    } else {
        g_find[n] = -1.0f;
        g_packres[n] = 0xFFFFFFFFFFFFFFFFull;
        int sl = atomicAdd(&g_wcount, 1);
        g_wlist[sl] = n;
    }
}

// ---------------------------------------------------------------------------
// Kernel 4: exact rescan as a compacted 3xTF32 mini-GEMM.
// Persistent grid 148 x 256. Block = (128 gathered rows) x (256-code quarter).
// Results merged via packed uint64 atomicMin (deterministic).
// smem: rowid[128] int | y2q[256] f | A4 [8][128][4] uint4 (64KB) | B 2x32KB
// ---------------------------------------------------------------------------
#define FX_ROWID 0
#define FX_Y2    512
#define FX_A     1536
#define FX_B     (FX_A + 65536)
#define FX_SMEM  (FX_B + 2 * 32768)

__global__ __launch_bounds__(256, 1)
void fix_kernel() {
    extern __shared__ char sm[];
    uint32_t sb = smem_u32(sm);
    int*   rowid = (int*)(sm + FX_ROWID);
    float* y2q   = (float*)(sm + FX_Y2);
    uint4* A4    = (uint4*)(sm + FX_A);
    int tid = threadIdx.x;
    int wid = tid >> 5, lane = tid & 31;
    int g = lane >> 2, tt = lane & 3;
    int cnt = g_wcount;
    int nrb = (cnt + 127) >> 7;
    int total = nrb * 4;

    for (int blk = blockIdx.x; blk < total; blk += gridDim.x) {
        int rb = blk >> 2;        // row block
        int q  = blk & 3;         // code quarter (256 codes)
        __syncthreads();          // protect smem reuse across iterations

        if (tid < 128) {
            int wi = rb * 128 + tid;
            rowid[tid] = (wi < cnt) ? g_wlist[wi] : -1;
        }
        if (tid < 256) y2q[tid] = g_y2[q * 256 + tid];
        __syncthreads();

        // A gather + hi/lo split into fragment layout [s][128][4]
        {
            int r = tid >> 1, hh = tid & 1;
            int n = rowid[r];
            #pragma unroll
            for (int si = 0; si < 4; ++si) {
                int s = hh * 4 + si;
                uint4 u0 = make_uint4(0, 0, 0, 0), u1 = u0, u2 = u0, u3 = u0;
                if (n >= 0) {
                    float4 fa = *(const float4*)&g_zf[n * 64 + s * 8];
                    float4 fb = *(const float4*)&g_zf[n * 64 + s * 8 + 4];
                    float v0[4] = {fa.x, fa.y, fa.z, fa.w};
                    float v1[4] = {fb.x, fb.y, fb.z, fb.w};
                    uint4 uu[4];
                    #pragma unroll
                    for (int t = 0; t < 4; ++t) {
                        uint32_t h0 = f2tf32(v0[t]), h1 = f2tf32(v1[t]);
                        uint32_t l0 = f2tf32(v0[t] - __uint_as_float(h0));
                        uint32_t l1 = f2tf32(v1[t] - __uint_as_float(h1));
                        uu[t] = make_uint4(h0, h1, l0, l1);
                    }
                    u0 = uu[0]; u1 = uu[1]; u2 = uu[2]; u3 = uu[3];
                }
                A4[(s * 128 + r) * 4 + 0] = u0;
                A4[(s * 128 + r) * 4 + 1] = u1;
                A4[(s * 128 + r) * 4 + 2] = u2;
                A4[(s * 128 + r) * 4 + 3] = u3;
            }
        }

        // prefetch B chunk 0
        {
            const uint4* src = g_bpack4 + (q * 4 + 0) * 2048;
            #pragma unroll
            for (int i = 0; i < 8; ++i) {
                int idx = i * 256 + tid;
                CP_ASYNC16(sb + FX_B + idx * 16, src + idx);
            }
            CP_COMMIT();
        }
        __syncthreads();

        float best0 = 3.4028235e38f, best1 = 3.4028235e38f;
        int   idx0 = 0, idx1 = 0;

        for (int ch = 0; ch < 4; ++ch) {
            int buf = ch & 1;
            if (ch + 1 < 4) {
                const uint4* src = g_bpack4 + (q * 4 + ch + 1) * 2048;
                uint32_t dst = sb + FX_B + (buf ^ 1) * 32768;
                #pragma unroll
                for (int i = 0; i < 8; ++i) {
                    int idx = i * 256 + tid;
                    CP_ASYNC16(dst + idx * 16, src + idx);
                }
                CP_COMMIT();
                CP_WAIT(1);
            } else {
                CP_WAIT(0);
            }
            __syncthreads();
            const uint4* Bb = (const uint4*)(sm + FX_B + buf * 32768);

            float acc[8][4];
            #pragma unroll
            for (int j = 0; j < 8; ++j)
                #pragma unroll
                for (int e = 0; e < 4; ++e) acc[j][e] = 0.f;

            #pragma unroll
            for (int s = 0; s < 8; ++s) {
                uint4 pa0 = A4[(s * 128 + wid * 16 + g) * 4 + tt];
                uint4 pa1 = A4[(s * 128 + wid * 16 + 8 + g) * 4 + tt];
                #pragma unroll
                for (int j = 0; j < 8; ++j) {
                    uint4 bq = Bb[s * 256 + (j * 8 + g) * 4 + tt];
                    mma16n8k8(acc[j], pa0.x, pa1.x, pa0.y, pa1.y, bq.x, bq.y); // hi*hi
                    mma16n8k8(acc[j], pa0.x, pa1.x, pa0.y, pa1.y, bq.z, bq.w); // hi*lo
                    mma16n8k8(acc[j], pa0.z, pa1.z, pa0.w, pa1.w, bq.x, bq.y); // lo*hi
                }
            }

            #pragma unroll
            for (int j = 0; j < 8; ++j) {
                int cl = ch * 64 + j * 8 + 2 * tt;       // within quarter
                float2 y = *(const float2*)&y2q[cl];
                int cg = q * 256 + cl;                    // global code
                float k0 = fmaf(acc[j][0], -2.0f, y.x);
                float k1 = fmaf(acc[j][1], -2.0f, y.y);
                float k2 = fmaf(acc[j][2], -2.0f, y.x);
                float k3 = fmaf(acc[j][3], -2.0f, y.y);
                if (k0 < best0) { best0 = k0; idx0 = cg; }
                if (k1 < best0) { best0 = k1; idx0 = cg + 1; }
                if (k2 < best1) { best1 = k2; idx1 = cg; }
                if (k3 < best1) { best1 = k3; idx1 = cg + 1; }
            }
            __syncthreads();     // all done with buf before next prefetch reuses it
        }

        // merge: direct packed atomicMin per (lane-row) candidate
        {
            int n0 = rowid[wid * 16 + g];
            int n8 = rowid[wid * 16 + 8 + g];
            if (n0 >= 0) atomicMin(&g_packres[n0], pack_key(best0, idx0));
            if (n8 >= 0) atomicMin(&g_packres[n8], pack_key(best1, idx1));
        }
    }
}

// ---------------------------------------------------------------------------
// Kernel 5: z_q with EXACT dmin (gather chosen code), output transpose,
// fixed-point loss. Grid 1024 x 256. Last CTA finalizes + resets counters.
// ---------------------------------------------------------------------------
__global__ __launch_bounds__(256)
void zq_kernel(const float* __restrict__ z,
               const float* __restrict__ noise,
               const float* __restrict__ cb,
               float* __restrict__ out,
               float* __restrict__ out_ind,
               float* __restrict__ out_loss) {
    __shared__ float zt[64][33];
    __shared__ float zq[32 * 65];
    __shared__ float sred[256];
    int t = threadIdx.x;
    int c = blockIdx.x;
    int b = c >> 5;
    int p = c & 31;
    int r0 = b * 1024 + p * 32;

    int row = t >> 3;
    int seg = t & 7;
    int n = r0 + row;

    float4 n0 = *(const float4*)&noise[n * 64 + seg * 8];
    float4 n1 = *(const float4*)&noise[n * 64 + seg * 8 + 4];
    float mi = g_find[n];
    int ci;
    if (mi < 0.f) {
        ci = (int)(g_packres[n] & 0xFFFFFFFFull);
        mi = (float)ci;
    } else {
        ci = (int)mi;
    }
    float y2c = g_y2[ci];
    float4 c0 = *(const float4*)&cb[ci * 64 + seg * 8];
    float4 c1 = *(const float4*)&cb[ci * 64 + seg * 8 + 4];

    {
        const float* zb = z + (size_t)b * 65536 + p * 32;
        int w = t & 31, db = t >> 5;
        #pragma unroll
        for (int it = 0; it < 8; ++it) {
            int d = it * 8 + db;
            zt[d][w] = zb[d * 1024 + w];
        }
    }
    __syncthreads();

    float nv[8] = {n0.x, n0.y, n0.z, n0.w, n1.x, n1.y, n1.z, n1.w};
    float cv[8] = {c0.x, c0.y, c0.z, c0.w, c1.x, c1.y, c1.z, c1.w};
    float zv[8];
    #pragma unroll
    for (int i = 0; i < 8; ++i) zv[i] = zt[seg * 8 + i][row];

    float s = 0.f, xs = 0.f, ds = 0.f;
    #pragma unroll
    for (int i = 0; i < 8; ++i) {
        s += nv[i] * nv[i];
        xs += zv[i] * zv[i];
        ds += zv[i] * cv[i];
    }
    s  += __shfl_down_sync(0xffffffffu, s, 4, 8);
    xs += __shfl_down_sync(0xffffffffu, xs, 4, 8);
    ds += __shfl_down_sync(0xffffffffu, ds, 4, 8);
    s  += __shfl_down_sync(0xffffffffu, s, 2, 8);
    xs += __shfl_down_sync(0xffffffffu, xs, 2, 8);
    ds += __shfl_down_sync(0xffffffffu, ds, 2, 8);
    s  += __shfl_down_sync(0xffffffffu, s, 1, 8);
    xs += __shfl_down_sync(0xffffffffu, xs, 1, 8);
    ds += __shfl_down_sync(0xffffffffu, ds, 1, 8);
    float norm2 = __shfl_sync(0xffffffffu, s, 0, 8);
    float x2    = __shfl_sync(0xffffffffu, xs, 0, 8);
    float dot   = __shfl_sync(0xffffffffu, ds, 0, 8);

    if (seg == 0) out_ind[n] = mi;

    float dmin = x2 + y2c - 2.0f * dot;
    float scale = sqrtf(fmaxf(dmin, 0.f)) / fmaxf(sqrtf(norm2), 1e-9f);

    float part = 0.f;
    #pragma unroll
    for (int i = 0; i < 8; ++i) {
        float qv = zv[i] + nv[i] * scale;
        part += qv;
        zq[row * 65 + seg * 8 + i] = qv;
    }
    sred[t] = part;
    __syncthreads();

    for (int off = 64; off > 0; off >>= 1) {
        if ((t & 127) < off) sred[t] += sred[t + off];
        __syncthreads();
    }
    if ((t & 127) == 0) {
        float sv = sred[t];
        unsigned long long qq =
            (unsigned long long)__double2ll_rn((double)sv * (double)sv * 4194304.0);
        atomicAdd(&g_lacc, qq);
    }

    {
        int dd = t >> 2;
        int rg = t & 3;
        float4 o0, o1;
        o0.x = zq[(rg * 8 + 0) * 65 + dd];
        o0.y = zq[(rg * 8 + 1) * 65 + dd];
        o0.z = zq[(rg * 8 + 2) * 65 + dd];
        o0.w = zq[(rg * 8 + 3) * 65 + dd];
        o1.x = zq[(rg * 8 + 4) * 65 + dd];
        o1.y = zq[(rg * 8 + 5) * 65 + dd];
        o1.z = zq[(rg * 8 + 6) * 65 + dd];
        o1.w = zq[(rg * 8 + 7) * 65 + dd];
        float* op = out + (size_t)b * 65536 + dd * 1024 + p * 32 + rg * 8;
        *(float4*)op = o0;
        *(float4*)(op + 4) = o1;
    }

    __syncthreads();
    if (t == 0) {
        __threadfence();
        int v = atomicAdd(&g_ctr, 1);
        if (v == (int)gridDim.x - 1) {
            unsigned long long tot = atomicAdd(&g_lacc, 0ull);
            *out_loss = (float)((double)tot * (1.0 / 4194304.0) * (1.0 / 33554432.0));
            g_lacc = 0ull;
            g_ctr = 0;
            g_wcount = 0;
        }
    }
}

// ---------------------------------------------------------------------------
extern "C" void kernel_launch(void* const* d_in, const int* in_sizes, int n_in,
                              void* d_out, int out_size) {
    const float* z     = (const float*)d_in[0];
    const float* cb    = (const float*)d_in[1];
    const float* noise = (const float*)d_in[2];
    float* out      = (float*)d_out;
    float* out_loss = out + ZQ_ELEMS;
    float* out_ind  = out + ZQ_ELEMS + 1;

    cudaFuncSetAttribute(gemm_argmin_kernel,
                         cudaFuncAttributeMaxDynamicSharedMemorySize, GEMM_SMEM);
    cudaFuncSetAttribute(fix_kernel,
                         cudaFuncAttributeMaxDynamicSharedMemorySize, FX_SMEM);

    bprep_kernel<<<128, 256>>>(cb);
    gemm_argmin_kernel<<<128, 512, GEMM_SMEM>>>(z);
    triage_kernel<<<128, 256>>>();
    fix_kernel<<<148, 256, FX_SMEM>>>();
    zq_kernel<<<1024, 256>>>(z, noise, cb, out, out_ind, out_loss);
}

// round 12
// speedup vs baseline: 16.0891x; 1.0208x over previous
#include <cuda_runtime.h>
#include <math.h>
#include <stdint.h>

// Problem constants
#define NROWS 32768   // B*H*W
#define DDIM  64
#define MCODE 1024
#define HWSZ  1024
#define ZQ_ELEMS 2097152

// Static device scratch
__device__ float g_b1[2 * NROWS];        // per code-half: best approx key
__device__ float g_b2[2 * NROWS];        // per code-half: 2nd-best approx key
__device__ float g_i1[2 * NROWS];        // per code-half: best idx (float)
__device__ float g_x2[NROWS];            // per-row squared norm
__device__ float g_find[NROWS];          // final idx (>=0) or -1 => see g_packres
__device__ unsigned long long g_packres[NROWS];  // packed (sortable key | idx)
__device__ float g_zf[NROWS * DDIM];     // compact fp32 rows (written by gemm)
__device__ float g_y2[MCODE];
__device__ int   g_y2max_i = 0;
__device__ unsigned long long g_lacc = 0ull;  // fixed-point sum of s^2 (scale 2^22)
__device__ int   g_ctr = 0;              // zq completion counter (self-resetting)
__device__ int   g_wcount = 0;           // ambiguous worklist count (self-resetting)
__device__ int   g_wlist[NROWS];
__device__ int   g_pair[64];             // per-row-block pair counters (self-resetting)
// Codebook hi-tf32 (gemm): [chunk16][s8][ci64][t4] uint2{h0,h1}
__device__ uint2 g_bh[16 * 2048];
// Codebook hi/lo tf32 (fix): [chunk16][s8][ci64][t4] uint4{h0,h1,l0,l1}
__device__ uint4 g_bpack4[16 * 2048];

// ---------------------------------------------------------------------------
// helpers
// ---------------------------------------------------------------------------
__device__ __forceinline__ uint32_t f2tf32(float a) {
    uint32_t r; asm("cvt.rna.tf32.f32 %0, %1;" : "=r"(r) : "f"(a)); return r;
}
__device__ __forceinline__ uint32_t smem_u32(const void* p) {
    uint32_t a;
    asm("{ .reg .u64 t; cvta.to.shared.u64 t, %1; cvt.u32.u64 %0, t; }"
        : "=r"(a) : "l"(p));
    return a;
}
__device__ __forceinline__ void bulk_g2s(uint32_t dst, const void* src,
                                         uint32_t bytes, uint32_t mbar) {
    asm volatile(
        "cp.async.bulk.shared::cta.global.mbarrier::complete_tx::bytes [%0], [%1], %2, [%3];"
        :: "r"(dst), "l"(src), "r"(bytes), "r"(mbar) : "memory");
}
__device__ __forceinline__ void mbar_init(uint32_t mbar, uint32_t cnt) {
    asm volatile("mbarrier.init.shared.b64 [%0], %1;" :: "r"(mbar), "r"(cnt) : "memory");
}
__device__ __forceinline__ void mbar_expect_tx(uint32_t mbar, uint32_t bytes) {
    asm volatile("mbarrier.arrive.expect_tx.shared.b64 _, [%0], %1;"
                 :: "r"(mbar), "r"(bytes) : "memory");
}
__device__ __forceinline__ void mbar_wait(uint32_t mbar, uint32_t parity) {
    uint32_t done;
    asm volatile(
        "{\n\t.reg .pred p;\n\t"
        "mbarrier.try_wait.parity.acquire.cta.shared::cta.b64 p, [%1], %2;\n\t"
        "selp.b32 %0, 1, 0, p;\n\t}"
        : "=r"(done) : "r"(mbar), "r"(parity) : "memory");
    while (!done) {
        asm volatile(
            "{\n\t.reg .pred p;\n\t"
            "mbarrier.try_wait.parity.acquire.cta.shared::cta.b64 p, [%1], %2, 0x989680;\n\t"
            "selp.b32 %0, 1, 0, p;\n\t}"
            : "=r"(done) : "r"(mbar), "r"(parity) : "memory");
    }
}
__device__ __forceinline__ void mma16n8k8(float* c, uint32_t a0, uint32_t a1,
                                          uint32_t a2, uint32_t a3,
                                          uint32_t b0, uint32_t b1) {
    asm volatile(
        "mma.sync.aligned.m16n8k8.row.col.f32.tf32.tf32.f32 "
        "{%0,%1,%2,%3}, {%4,%5,%6,%7}, {%8,%9}, {%0,%1,%2,%3};"
        : "+f"(c[0]), "+f"(c[1]), "+f"(c[2]), "+f"(c[3])
        : "r"(a0), "r"(a1), "r"(a2), "r"(a3), "r"(b0), "r"(b1));
}
#define CP_ASYNC16(dst, src) \
    asm volatile("cp.async.cg.shared.global [%0], [%1], 16;" :: "r"(dst), "l"(src))
#define CP_COMMIT() asm volatile("cp.async.commit_group;" ::: "memory")
#define CP_WAIT(n)  asm volatile("cp.async.wait_group %0;" :: "n"(n) : "memory")

// float key -> order-preserving uint32 (handles negatives)
__device__ __forceinline__ unsigned long long pack_key(float k, int idx) {
    uint32_t u = __float_as_uint(k);
    u = (u & 0x80000000u) ? ~u : (u | 0x80000000u);
    return ((unsigned long long)u << 32) | (uint32_t)idx;
}

// ---------------------------------------------------------------------------
// Kernel 1: pack codebook (hi uint2 for gemm; hi/lo uint4 for fix) + y2.
// ---------------------------------------------------------------------------
__global__ void bprep_kernel(const float* __restrict__ cb) {
    int g = blockIdx.x * 256 + threadIdx.x;
    int c = g >> 5, s = (g >> 2) & 7, t = g & 3;
    float v0 = cb[c * DDIM + s * 8 + t];
    float v1 = cb[c * DDIM + s * 8 + t + 4];
    uint32_t h0 = f2tf32(v0), h1 = f2tf32(v1);
    uint32_t l0 = f2tf32(v0 - __uint_as_float(h0));
    uint32_t l1 = f2tf32(v1 - __uint_as_float(h1));
    int chunk = c >> 6, ci = c & 63;
    int off = chunk * 2048 + s * 256 + ci * 4 + t;
    g_bh[off] = make_uint2(h0, h1);
    g_bpack4[off] = make_uint4(h0, h1, l0, l1);
    float y = v0 * v0 + v1 * v1;
    #pragma unroll
    for (int d = 16; d > 0; d >>= 1)
        y += __shfl_xor_sync(0xffffffffu, y, d);
    if ((threadIdx.x & 31) == 0) {
        g_y2[c] = y;
        atomicMax(&g_y2max_i, __float_as_int(y));
    }
}

// ---------------------------------------------------------------------------
// Kernel 2: 1-pass TF32 gemm + best/2nd-best + compact zf + INLINE TRIAGE
// (second-finishing CTA of each row-block pair triages its 512 rows).
// ---------------------------------------------------------------------------
#define SM_MB   0
#define SM_Y2   128
#define SM_A    2176
#define SM_B    133248
#define GEMM_SMEM 166016

__global__ __launch_bounds__(512, 1)
void gemm_argmin_kernel(const float* __restrict__ z) {
    extern __shared__ char sm[];
    __shared__ int s_last;
    uint32_t sb = smem_u32(sm);
    uint2* A2 = (uint2*)(sm + SM_A);
    const float* y2s = (const float*)(sm + SM_Y2);
    int tid = threadIdx.x;
    int wid = tid >> 5, lane = tid & 31;
    int g = lane >> 2, tt = lane & 3;
    int half = blockIdx.x & 1;
    int rb = blockIdx.x >> 1;
    int r0 = rb * 512;
    int w32 = wid * 32;
    const uint2* bsrc = g_bh + half * 16384;

    if (tid == 0) {
        mbar_init(sb + SM_MB + 0, 1);
        mbar_init(sb + SM_MB + 8, 1);
    }
    __syncthreads();

    if (tid == 0) {
        mbar_expect_tx(sb + SM_MB + 0, 16384);
        bulk_g2s(sb + SM_B, bsrc, 16384, sb + SM_MB + 0);
        mbar_expect_tx(sb + SM_MB + 8, 16384);
        bulk_g2s(sb + SM_B + 16384, bsrc + 2048, 16384, sb + SM_MB + 8);
    }

    // A prep: z -> hi tf32 pairs + x2 + compact zf (half 0 writes)
    {
        const float* zb = z + (size_t)(rb >> 1) * (DDIM * HWSZ) + (rb & 1) * 512;
        int roff = lane >> 2, tp = lane & 3;
        #pragma unroll
        for (int p = 0; p < 4; ++p) {
            int r = p * 128 + wid * 8 + roff;
            float sq = 0.f;
            #pragma unroll
            for (int s = 0; s < 8; ++s) {
                float v0 = zb[(s * 8 + tp) * HWSZ + r];
                float v1 = zb[(s * 8 + tp + 4) * HWSZ + r];
                sq += v0 * v0 + v1 * v1;
                A2[(s * 512 + r) * 4 + tp] = make_uint2(f2tf32(v0), f2tf32(v1));
                if (half == 0) {
                    g_zf[(r0 + r) * 64 + s * 8 + tp] = v0;
                    g_zf[(r0 + r) * 64 + s * 8 + tp + 4] = v1;
                }
            }
            sq += __shfl_xor_sync(0xffffffffu, sq, 1);
            sq += __shfl_xor_sync(0xffffffffu, sq, 2);
            if (tp == 0 && half == 0) g_x2[r0 + r] = sq;
        }
    }
    for (int i = tid; i < 512; i += 512)
        ((float*)(sm + SM_Y2))[i] = g_y2[half * 512 + i];
    __syncthreads();

    float best[4], bst2[4];
    int   bidx[4];
    #pragma unroll
    for (int i = 0; i < 4; ++i) { best[i] = 3.4028235e38f; bst2[i] = 3.4028235e38f; bidx[i] = 0; }

    for (int ch = 0; ch < 8; ++ch) {
        int buf = ch & 1;
        mbar_wait(sb + SM_MB + buf * 8, (ch >> 1) & 1);
        const uint2* Bb = (const uint2*)(sm + SM_B + buf * 16384);

        float acc[2][8][4];
        #pragma unroll
        for (int m = 0; m < 2; ++m)
            #pragma unroll
            for (int j = 0; j < 8; ++j)
                #pragma unroll
                for (int e = 0; e < 4; ++e) acc[m][j][e] = 0.f;

        #pragma unroll
        for (int s = 0; s < 8; ++s) {
            uint2 a0 = A2[(s * 512 + w32 + g) * 4 + tt];
            uint2 a1 = A2[(s * 512 + w32 + 8 + g) * 4 + tt];
            uint2 a2 = A2[(s * 512 + w32 + 16 + g) * 4 + tt];
            uint2 a3 = A2[(s * 512 + w32 + 24 + g) * 4 + tt];
            #pragma unroll
            for (int j = 0; j < 8; ++j) {
                uint2 bq = Bb[s * 256 + (j * 8 + g) * 4 + tt];
                mma16n8k8(acc[0][j], a0.x, a1.x, a0.y, a1.y, bq.x, bq.y);
                mma16n8k8(acc[1][j], a2.x, a3.x, a2.y, a3.y, bq.x, bq.y);
            }
        }

        #pragma unroll
        for (int j = 0; j < 8; ++j) {
            int cl = ch * 64 + j * 8 + 2 * tt;
            float2 y = ((const float2*)y2s)[cl >> 1];
            #pragma unroll
            for (int m = 0; m < 2; ++m) {
                float k0 = fmaf(acc[m][j][0], -2.0f, y.x);
                float k1 = fmaf(acc[m][j][1], -2.0f, y.y);
                float k2 = fmaf(acc[m][j][2], -2.0f, y.x);
                float k3 = fmaf(acc[m][j][3], -2.0f, y.y);
                int s0 = m * 2, s1 = m * 2 + 1;
                if (k0 < best[s0]) { bst2[s0] = best[s0]; best[s0] = k0; bidx[s0] = cl; }
                else if (k0 < bst2[s0]) bst2[s0] = k0;
                if (k1 < best[s0]) { bst2[s0] = best[s0]; best[s0] = k1; bidx[s0] = cl + 1; }
                else if (k1 < bst2[s0]) bst2[s0] = k1;
                if (k2 < best[s1]) { bst2[s1] = best[s1]; best[s1] = k2; bidx[s1] = cl; }
                else if (k2 < bst2[s1]) bst2[s1] = k2;
                if (k3 < best[s1]) { bst2[s1] = best[s1]; best[s1] = k3; bidx[s1] = cl + 1; }
                else if (k3 < bst2[s1]) bst2[s1] = k3;
            }
        }

        __syncthreads();
        if (ch + 2 < 8 && tid == 0) {
            mbar_expect_tx(sb + SM_MB + buf * 8, 16384);
            bulk_g2s(sb + SM_B + buf * 16384, bsrc + (ch + 2) * 2048, 16384,
                     sb + SM_MB + buf * 8);
        }
    }

    #pragma unroll
    for (int m = 0; m < 4; ++m) {
        float b1 = best[m], b2 = bst2[m];
        int i1 = bidx[m];
        #pragma unroll
        for (int d = 1; d < 4; d <<= 1) {
            float ob1 = __shfl_xor_sync(0xffffffffu, b1, d);
            int   oi1 = __shfl_xor_sync(0xffffffffu, i1, d);
            float ob2 = __shfl_xor_sync(0xffffffffu, b2, d);
            float nb2 = fminf(fmaxf(b1, ob1), fminf(b2, ob2));
            if (ob1 < b1 || (ob1 == b1 && oi1 < i1)) { b1 = ob1; i1 = oi1; }
            b2 = nb2;
        }
        if (tt == 0) {
            int row = r0 + w32 + (m >> 1) * 16 + (m & 1) * 8 + g;
            g_b1[half * NROWS + row] = b1;
            g_b2[half * NROWS + row] = b2;
            g_i1[half * NROWS + row] = (float)(half * 512 + i1);
        }
    }

    // ---- pair-completion triage (second CTA of this row-block pair) ----
    __syncthreads();
    if (tid == 0) {
        __threadfence();                           // release our global writes
        int prev = atomicAdd(&g_pair[rb], 1);
        if (prev == 1) __threadfence();            // acquire peer's writes
        s_last = (prev == 1);
    }
    __syncthreads();
    if (s_last) {
        int n = r0 + tid;                          // 512 threads x 1 row
        float b10 = g_b1[n],         b11 = g_b1[NROWS + n];
        float b20 = g_b2[n],         b21 = g_b2[NROWS + n];
        float i10 = g_i1[n],         i11 = g_i1[NROWS + n];
        float fb, fi, fs;
        if (b11 < b10) { fb = b11; fi = i11; fs = fminf(b10, b21); }
        else           { fb = b10; fi = i10; fs = fminf(b11, b20); }
        float y2max = __int_as_float(g_y2max_i);
        float eps = 0.006f * sqrtf(g_x2[n] * y2max) + 1e-3f;
        if (fs - fb > eps) {
            g_find[n] = fi;
        } else {
            g_find[n] = -1.0f;
            g_packres[n] = 0xFFFFFFFFFFFFFFFFull;
            int sl = atomicAdd(&g_wcount, 1);
            g_wlist[sl] = n;
        }
        if (tid == 0) g_pair[rb] = 0;              // self-reset for next replay
    }
}

// ---------------------------------------------------------------------------
// Kernel 3: exact rescan as compacted 3xTF32 mini-GEMM.
// Block = (64 gathered rows) x (256-code quarter); grid 296 (2 CTAs/SM).
// 8 warps: m-tile = wid&3 (16 rows), code-subset = wid>>2 (32 of 64/chunk).
// Results merged via packed uint64 atomicMin (deterministic).
// smem: rowid[64] | y2q[256] | A4 [8][64][4] uint4 (32KB) | B 2x32KB = ~99.8KB
// ---------------------------------------------------------------------------
#define FX_ROWID 0
#define FX_Y2    256
#define FX_A     1536
#define FX_B     (FX_A + 32768)
#define FX_SMEM  (FX_B + 2 * 32768)

__global__ __launch_bounds__(256, 2)
void fix_kernel() {
    extern __shared__ char sm[];
    uint32_t sb = smem_u32(sm);
    int*   rowid = (int*)(sm + FX_ROWID);
    float* y2q   = (float*)(sm + FX_Y2);
    uint4* A4    = (uint4*)(sm + FX_A);
    int tid = threadIdx.x;
    int wid = tid >> 5, lane = tid & 31;
    int g = lane >> 2, tt = lane & 3;
    int mt = wid & 3;          // m-tile (16 rows)
    int jh = wid >> 2;         // code subset within chunk (j 0-3 | 4-7)
    int cnt = g_wcount;
    int nrb = (cnt + 63) >> 6;
    int total = nrb * 4;

    for (int blk = blockIdx.x; blk < total; blk += gridDim.x) {
        int rb = blk >> 2;
        int q  = blk & 3;
        __syncthreads();       // protect smem reuse across grid-stride iters

        if (tid < 64) {
            int wi = rb * 64 + tid;
            rowid[tid] = (wi < cnt) ? g_wlist[wi] : -1;
        }
        y2q[tid] = g_y2[q * 256 + tid];
        __syncthreads();

        // A gather + hi/lo split: thread = (row r = tid>>2, s-pair = tid&3)
        {
            int r = tid >> 2, sp = tid & 3;
            int n = rowid[r];
            #pragma unroll
            for (int si = 0; si < 2; ++si) {
                int s = sp * 2 + si;
                uint4 uu[4];
                if (n >= 0) {
                    float4 fa = *(const float4*)&g_zf[n * 64 + s * 8];
                    float4 fb = *(const float4*)&g_zf[n * 64 + s * 8 + 4];
                    float v0[4] = {fa.x, fa.y, fa.z, fa.w};
                    float v1[4] = {fb.x, fb.y, fb.z, fb.w};
                    #pragma unroll
                    for (int t = 0; t < 4; ++t) {
                        uint32_t h0 = f2tf32(v0[t]), h1 = f2tf32(v1[t]);
                        uint32_t l0 = f2tf32(v0[t] - __uint_as_float(h0));
                        uint32_t l1 = f2tf32(v1[t] - __uint_as_float(h1));
                        uu[t] = make_uint4(h0, h1, l0, l1);
                    }
                } else {
                    #pragma unroll
                    for (int t = 0; t < 4; ++t) uu[t] = make_uint4(0, 0, 0, 0);
                }
                #pragma unroll
                for (int t = 0; t < 4; ++t)
                    A4[(s * 64 + r) * 4 + t] = uu[t];
            }
        }

        // prefetch B chunk 0 (2048 uint4 = 32KB)
        {
            const uint4* src = g_bpack4 + (q * 4 + 0) * 2048;
            #pragma unroll
            for (int i = 0; i < 8; ++i) {
                int idx = i * 256 + tid;
                CP_ASYNC16(sb + FX_B + idx * 16, src + idx);
            }
            CP_COMMIT();
        }
        __syncthreads();

        float best0 = 3.4028235e38f, best1 = 3.4028235e38f;
        int   idx0 = 0, idx1 = 0;

        for (int ch = 0; ch < 4; ++ch) {
            int buf = ch & 1;
            if (ch + 1 < 4) {
                const uint4* src = g_bpack4 + (q * 4 + ch + 1) * 2048;
                uint32_t dst = sb + FX_B + (buf ^ 1) * 32768;
                #pragma unroll
                for (int i = 0; i < 8; ++i) {
                    int idx = i * 256 + tid;
                    CP_ASYNC16(dst + idx * 16, src + idx);
                }
                CP_COMMIT();
                CP_WAIT(1);
            } else {
                CP_WAIT(0);
            }
            __syncthreads();
            const uint4* Bb = (const uint4*)(sm + FX_B + buf * 32768);

            float acc[4][4];
            #pragma unroll
            for (int j = 0; j < 4; ++j)
                #pragma unroll
                for (int e = 0; e < 4; ++e) acc[j][e] = 0.f;

            #pragma unroll
            for (int s = 0; s < 8; ++s) {
                uint4 pa0 = A4[(s * 64 + mt * 16 + g) * 4 + tt];
                uint4 pa1 = A4[(s * 64 + mt * 16 + 8 + g) * 4 + tt];
                #pragma unroll
                for (int j = 0; j < 4; ++j) {
                    int jj = jh * 4 + j;
                    uint4 bq = Bb[s * 256 + (jj * 8 + g) * 4 + tt];
                    mma16n8k8(acc[j], pa0.x, pa1.x, pa0.y, pa1.y, bq.x, bq.y); // hi*hi
                    mma16n8k8(acc[j], pa0.x, pa1.x, pa0.y, pa1.y, bq.z, bq.w); // hi*lo
                    mma16n8k8(acc[j], pa0.z, pa1.z, pa0.w, pa1.w, bq.x, bq.y); // lo*hi
                }
            }

            #pragma unroll
            for (int j = 0; j < 4; ++j) {
                int jj = jh * 4 + j;
                int cl = ch * 64 + jj * 8 + 2 * tt;
                float2 y = *(const float2*)&y2q[cl];
                int cg = q * 256 + cl;
                float k0 = fmaf(acc[j][0], -2.0f, y.x);
                float k1 = fmaf(acc[j][1], -2.0f, y.y);
                float k2 = fmaf(acc[j][2], -2.0f, y.x);
                float k3 = fmaf(acc[j][3], -2.0f, y.y);
                if (k0 < best0) { best0 = k0; idx0 = cg; }
                if (k1 < best0) { best0 = k1; idx0 = cg + 1; }
                if (k2 < best1) { best1 = k2; idx1 = cg; }
                if (k3 < best1) { best1 = k3; idx1 = cg + 1; }
            }
            __syncthreads();
        }

        // merge: packed atomicMin per candidate row
        {
            int n0 = rowid[mt * 16 + g];
            int n8 = rowid[mt * 16 + 8 + g];
            if (n0 >= 0) atomicMin(&g_packres[n0], pack_key(best0, idx0));
            if (n8 >= 0) atomicMin(&g_packres[n8], pack_key(best1, idx1));
        }
    }
}

// ---------------------------------------------------------------------------
// Kernel 4: z_q with EXACT dmin (gather chosen code), output transpose,
// fixed-point loss. Grid 1024 x 256. Last CTA finalizes + resets counters.
// ---------------------------------------------------------------------------
__global__ __launch_bounds__(256)
void zq_kernel(const float* __restrict__ z,
               const float* __restrict__ noise,
               const float* __restrict__ cb,
               float* __restrict__ out,
               float* __restrict__ out_ind,
               float* __restrict__ out_loss) {
    __shared__ float zt[64][33];
    __shared__ float zq[32 * 65];
    __shared__ float sred[256];
    int t = threadIdx.x;
    int c = blockIdx.x;
    int b = c >> 5;
    int p = c & 31;
    int r0 = b * 1024 + p * 32;

    int row = t >> 3;
    int seg = t & 7;
    int n = r0 + row;

    float4 n0 = *(const float4*)&noise[n * 64 + seg * 8];
    float4 n1 = *(const float4*)&noise[n * 64 + seg * 8 + 4];
    float mi = g_find[n];
    int ci;
    if (mi < 0.f) {
        ci = (int)(g_packres[n] & 0xFFFFFFFFull);
        mi = (float)ci;
    } else {
        ci = (int)mi;
    }
    float y2c = g_y2[ci];
    float4 c0 = *(const float4*)&cb[ci * 64 + seg * 8];
    float4 c1 = *(const float4*)&cb[ci * 64 + seg * 8 + 4];

    {
        const float* zb = z + (size_t)b * 65536 + p * 32;
        int w = t & 31, db = t >> 5;
        #pragma unroll
        for (int it = 0; it < 8; ++it) {
            int d = it * 8 + db;
            zt[d][w] = zb[d * 1024 + w];
        }
    }
    __syncthreads();

    float nv[8] = {n0.x, n0.y, n0.z, n0.w, n1.x, n1.y, n1.z, n1.w};
    float cv[8] = {c0.x, c0.y, c0.z, c0.w, c1.x, c1.y, c1.z, c1.w};
    float zv[8];
    #pragma unroll
    for (int i = 0; i < 8; ++i) zv[i] = zt[seg * 8 + i][row];

    float s = 0.f, xs = 0.f, ds = 0.f;
    #pragma unroll
    for (int i = 0; i < 8; ++i) {
        s += nv[i] * nv[i];
        xs += zv[i] * zv[i];
        ds += zv[i] * cv[i];
    }
    s  += __shfl_down_sync(0xffffffffu, s, 4, 8);
    xs += __shfl_down_sync(0xffffffffu, xs, 4, 8);
    ds += __shfl_down_sync(0xffffffffu, ds, 4, 8);
    s  += __shfl_down_sync(0xffffffffu, s, 2, 8);
    xs += __shfl_down_sync(0xffffffffu, xs, 2, 8);
    ds += __shfl_down_sync(0xffffffffu, ds, 2, 8);
    s  += __shfl_down_sync(0xffffffffu, s, 1, 8);
    xs += __shfl_down_sync(0xffffffffu, xs, 1, 8);
    ds += __shfl_down_sync(0xffffffffu, ds, 1, 8);
    float norm2 = __shfl_sync(0xffffffffu, s, 0, 8);
    float x2    = __shfl_sync(0xffffffffu, xs, 0, 8);
    float dot   = __shfl_sync(0xffffffffu, ds, 0, 8);

    if (seg == 0) out_ind[n] = mi;

    float dmin = x2 + y2c - 2.0f * dot;
    float scale = sqrtf(fmaxf(dmin, 0.f)) / fmaxf(sqrtf(norm2), 1e-9f);

    float part = 0.f;
    #pragma unroll
    for (int i = 0; i < 8; ++i) {
        float qv = zv[i] + nv[i] * scale;
        part += qv;
        zq[row * 65 + seg * 8 + i] = qv;
    }
    sred[t] = part;
    __syncthreads();

    for (int off = 64; off > 0; off >>= 1) {
        if ((t & 127) < off) sred[t] += sred[t + off];
        __syncthreads();
    }
    if ((t & 127) == 0) {
        float sv = sred[t];
        unsigned long long qq =
            (unsigned long long)__double2ll_rn((double)sv * (double)sv * 4194304.0);
        atomicAdd(&g_lacc, qq);
    }

    {
        int dd = t >> 2;
        int rg = t & 3;
        float4 o0, o1;
        o0.x = zq[(rg * 8 + 0) * 65 + dd];
        o0.y = zq[(rg * 8 + 1) * 65 + dd];
        o0.z = zq[(rg * 8 + 2) * 65 + dd];
        o0.w = zq[(rg * 8 + 3) * 65 + dd];
        o1.x = zq[(rg * 8 + 4) * 65 + dd];
        o1.y = zq[(rg * 8 + 5) * 65 + dd];
        o1.z = zq[(rg * 8 + 6) * 65 + dd];
        o1.w = zq[(rg * 8 + 7) * 65 + dd];
        float* op = out + (size_t)b * 65536 + dd * 1024 + p * 32 + rg * 8;
        *(float4*)op = o0;
        *(float4*)(op + 4) = o1;
    }

    __syncthreads();
    if (t == 0) {
        __threadfence();
        int v = atomicAdd(&g_ctr, 1);
        if (v == (int)gridDim.x - 1) {
            unsigned long long tot = atomicAdd(&g_lacc, 0ull);
            *out_loss = (float)((double)tot * (1.0 / 4194304.0) * (1.0 / 33554432.0));
            g_lacc = 0ull;
            g_ctr = 0;
            g_wcount = 0;
        }
    }
}

// ---------------------------------------------------------------------------
extern "C" void kernel_launch(void* const* d_in, const int* in_sizes, int n_in,
                              void* d_out, int out_size) {
    const float* z     = (const float*)d_in[0];
    const float* cb    = (const float*)d_in[1];
    const float* noise = (const float*)d_in[2];
    float* out      = (float*)d_out;
    float* out_loss = out + ZQ_ELEMS;
    float* out_ind  = out + ZQ_ELEMS + 1;

    cudaFuncSetAttribute(gemm_argmin_kernel,
                         cudaFuncAttributeMaxDynamicSharedMemorySize, GEMM_SMEM);
    cudaFuncSetAttribute(fix_kernel,
                         cudaFuncAttributeMaxDynamicSharedMemorySize, FX_SMEM);

    bprep_kernel<<<128, 256>>>(cb);
    gemm_argmin_kernel<<<128, 512, GEMM_SMEM>>>(z);
    fix_kernel<<<296, 256, FX_SMEM>>>();
    zq_kernel<<<1024, 256>>>(z, noise, cb, out, out_ind, out_loss);
}

// round 13
// speedup vs baseline: 16.6354x; 1.0340x over previous
#include <cuda_runtime.h>
#include <math.h>
#include <stdint.h>

// Problem constants
#define NROWS 32768   // B*H*W
#define DDIM  64
#define MCODE 1024
#define HWSZ  1024
#define ZQ_ELEMS 2097152

// Static device scratch
__device__ float g_key[2 * NROWS];       // per code-half: min key (y2 - 2*dot)
__device__ float g_kidx[2 * NROWS];      // per code-half: argmin index (as float)
__device__ unsigned long long g_lacc = 0ull;  // fixed-point sum of s^2 (scale 2^22)
__device__ int   g_ctr = 0;              // zq completion counter (self-resetting)

// ---------------------------------------------------------------------------
// helpers
// ---------------------------------------------------------------------------
__device__ __forceinline__ uint32_t f2tf32(float a) {
    uint32_t r; asm("cvt.rna.tf32.f32 %0, %1;" : "=r"(r) : "f"(a)); return r;
}
// D = A(16x8) * B(8x8) + C, tf32, fp32 accum
__device__ __forceinline__ void mma16n8k8(float* c, uint32_t a0, uint32_t a1,
                                          uint32_t a2, uint32_t a3,
                                          uint32_t b0, uint32_t b1) {
    asm volatile(
        "mma.sync.aligned.m16n8k8.row.col.f32.tf32.tf32.f32 "
        "{%0,%1,%2,%3}, {%4,%5,%6,%7}, {%8,%9}, {%0,%1,%2,%3};"
        : "+f"(c[0]), "+f"(c[1]), "+f"(c[2]), "+f"(c[3])
        : "r"(a0), "r"(a1), "r"(a2), "r"(a3), "r"(b0), "r"(b1));
}

// Pack one (code bc, kstep bs) pair of float4s into the hi/lo tf32 fragment
// smem layout (row stride 257 uint4 to spread store banks), and accumulate
// the code's y2 via a deterministic 8-lane tree (lanes = bs groups).
__device__ __forceinline__ void pack_chunk(uint4* bdst, float* y2dst,
                                           int bc, int bs, float4 fa, float4 fb) {
    float v0[4] = {fa.x, fa.y, fa.z, fa.w};
    float v1[4] = {fb.x, fb.y, fb.z, fb.w};
    float part = 0.f;
    #pragma unroll
    for (int t = 0; t < 4; ++t) {
        uint32_t h0 = f2tf32(v0[t]), h1 = f2tf32(v1[t]);
        uint32_t l0 = f2tf32(v0[t] - __uint_as_float(h0));
        uint32_t l1 = f2tf32(v1[t] - __uint_as_float(h1));
        bdst[bs * 257 + bc * 4 + t] = make_uint4(h0, h1, l0, l1);
        part += v0[t] * v0[t] + v1[t] * v1[t];
    }
    part += __shfl_down_sync(0xffffffffu, part, 4, 8);
    part += __shfl_down_sync(0xffffffffu, part, 2, 8);
    part += __shfl_down_sync(0xffffffffu, part, 1, 8);
    if (bs == 0) y2dst[bc] = part;
}

// ---------------------------------------------------------------------------
// Kernel 1: 3xTF32 mma.sync distance GEMM + fused argmin + IN-CTA codebook
// packing (no separate prep kernel; raw cb LDG prefetched under the MMA).
// Grid 128: bit0 = code half (512 codes), bits1+ = row block (512 rows).
// 512 threads = 16 warps x 32 rows. 8 chunks of 64 codes.
// smem: y2c[2][64] | A2 float2[8][512][4] (128KB) | Bpack 2 x 8*257 uint4.
// ---------------------------------------------------------------------------
#define SM_Y2   0
#define SM_A    1024
#define SM_B    132096
#define BBUF_U4 2056                  // 8 * 257 uint4 per buffer (32896 B)
#define GEMM_SMEM (132096 + 2 * 32896)   // 197888

__global__ __launch_bounds__(512, 1)
void gemm_argmin_kernel(const float* __restrict__ z, const float* __restrict__ cb) {
    extern __shared__ char sm[];
    float*  y2c   = (float*)(sm + SM_Y2);
    float2* A2    = (float2*)(sm + SM_A);
    uint4*  Bpack = (uint4*)(sm + SM_B);
    int tid = threadIdx.x;
    int wid = tid >> 5, lane = tid & 31;
    int g = lane >> 2, tt = lane & 3;
    int half = blockIdx.x & 1;
    int rb = blockIdx.x >> 1;            // 0..63
    int r0 = rb * 512;
    int w32 = wid * 32;
    const float* cbh = cb + (size_t)half * 512 * DDIM;
    int bc = tid >> 3;                   // code within chunk (0..63)
    int bs = tid & 7;                    // k-step (0..7)

    // prologue: LDG raw B chunk 0 (coalesced: 8 threads cover one code row)
    float4 c0 = *(const float4*)&cbh[(size_t)bc * DDIM + bs * 8];
    float4 c1 = *(const float4*)&cbh[(size_t)bc * DDIM + bs * 8 + 4];

    // A prep: z[b, d, hw0 + r] -> A2[(s*512 + r)*4 + t] = {f(k=8s+t), f(k=8s+t+4)}
    {
        const float* zb = z + (size_t)(rb >> 1) * (DDIM * HWSZ) + (rb & 1) * 512;
        int roff = lane >> 2, tp = lane & 3;
        #pragma unroll
        for (int p = 0; p < 4; ++p) {
            int r = p * 128 + wid * 8 + roff;
            #pragma unroll
            for (int s = 0; s < 8; ++s) {
                float v0 = zb[(s * 8 + tp) * HWSZ + r];
                float v1 = zb[(s * 8 + tp + 4) * HWSZ + r];
                A2[(s * 512 + r) * 4 + tp] = make_float2(v0, v1);
            }
        }
    }

    // pack chunk 0 into buffer 0
    pack_chunk(Bpack, y2c, bc, bs, c0, c1);
    __syncthreads();

    float best[4];
    int   bidx[4];
    #pragma unroll
    for (int i = 0; i < 4; ++i) { best[i] = 3.4028235e38f; bidx[i] = 0; }

    for (int ch = 0; ch < 8; ++ch) {
        int buf = ch & 1;
        // prefetch raw B chunk ch+1 into registers (latency hidden by MMA)
        float4 p0, p1;
        if (ch < 7) {
            const float* src = &cbh[(size_t)((ch + 1) * 64 + bc) * DDIM + bs * 8];
            p0 = *(const float4*)src;
            p1 = *(const float4*)(src + 4);
        }
        const uint4* Bb  = Bpack + buf * BBUF_U4;
        const float* y2b = y2c + buf * 64;

        float acc[2][8][4];
        #pragma unroll
        for (int m = 0; m < 2; ++m)
            #pragma unroll
            for (int j = 0; j < 8; ++j)
                #pragma unroll
                for (int e = 0; e < 4; ++e) acc[m][j][e] = 0.f;

        #pragma unroll
        for (int s = 0; s < 8; ++s) {
            float2 f0 = A2[(s * 512 + w32 + g) * 4 + tt];
            float2 f1 = A2[(s * 512 + w32 + 8 + g) * 4 + tt];
            float2 f2 = A2[(s * 512 + w32 + 16 + g) * 4 + tt];
            float2 f3 = A2[(s * 512 + w32 + 24 + g) * 4 + tt];
            uint32_t h0x = f2tf32(f0.x), h0y = f2tf32(f0.y);
            uint32_t h1x = f2tf32(f1.x), h1y = f2tf32(f1.y);
            uint32_t h2x = f2tf32(f2.x), h2y = f2tf32(f2.y);
            uint32_t h3x = f2tf32(f3.x), h3y = f2tf32(f3.y);
            uint32_t l0x = f2tf32(f0.x - __uint_as_float(h0x));
            uint32_t l0y = f2tf32(f0.y - __uint_as_float(h0y));
            uint32_t l1x = f2tf32(f1.x - __uint_as_float(h1x));
            uint32_t l1y = f2tf32(f1.y - __uint_as_float(h1y));
            uint32_t l2x = f2tf32(f2.x - __uint_as_float(h2x));
            uint32_t l2y = f2tf32(f2.y - __uint_as_float(h2y));
            uint32_t l3x = f2tf32(f3.x - __uint_as_float(h3x));
            uint32_t l3y = f2tf32(f3.y - __uint_as_float(h3y));
            #pragma unroll
            for (int j = 0; j < 8; ++j) {
                uint4 bq = Bb[s * 257 + (j * 8 + g) * 4 + tt];
                mma16n8k8(acc[0][j], h0x, h1x, h0y, h1y, bq.x, bq.y);  // hi*hi
                mma16n8k8(acc[0][j], h0x, h1x, h0y, h1y, bq.z, bq.w);  // hi*lo
                mma16n8k8(acc[0][j], l0x, l1x, l0y, l1y, bq.x, bq.y);  // lo*hi
                mma16n8k8(acc[1][j], h2x, h3x, h2y, h3y, bq.x, bq.y);
                mma16n8k8(acc[1][j], h2x, h3x, h2y, h3y, bq.z, bq.w);
                mma16n8k8(acc[1][j], l2x, l3x, l2y, l3y, bq.x, bq.y);
            }
        }

        // epilogue: key = y2 - 2*dot, running argmin (first-occurrence ties)
        #pragma unroll
        for (int j = 0; j < 8; ++j) {
            int cl = ch * 64 + j * 8 + 2 * tt;
            float2 y = *(const float2*)&y2b[j * 8 + 2 * tt];
            float k0 = fmaf(acc[0][j][0], -2.0f, y.x);
            float k1 = fmaf(acc[0][j][1], -2.0f, y.y);
            float k2 = fmaf(acc[0][j][2], -2.0f, y.x);
            float k3 = fmaf(acc[0][j][3], -2.0f, y.y);
            float k4 = fmaf(acc[1][j][0], -2.0f, y.x);
            float k5 = fmaf(acc[1][j][1], -2.0f, y.y);
            float k6 = fmaf(acc[1][j][2], -2.0f, y.x);
            float k7 = fmaf(acc[1][j][3], -2.0f, y.y);
            if (k0 < best[0]) { best[0] = k0; bidx[0] = cl; }
            if (k1 < best[0]) { best[0] = k1; bidx[0] = cl + 1; }
            if (k2 < best[1]) { best[1] = k2; bidx[1] = cl; }
            if (k3 < best[1]) { best[1] = k3; bidx[1] = cl + 1; }
            if (k4 < best[2]) { best[2] = k4; bidx[2] = cl; }
            if (k5 < best[2]) { best[2] = k5; bidx[2] = cl + 1; }
            if (k6 < best[3]) { best[3] = k6; bidx[3] = cl; }
            if (k7 < best[3]) { best[3] = k7; bidx[3] = cl + 1; }
        }

        __syncthreads();                 // all reads of buf & y2c[buf] done
        if (ch < 7) {
            pack_chunk(Bpack + (buf ^ 1) * BBUF_U4, y2c + (buf ^ 1) * 64,
                       bc, bs, p0, p1);
            __syncthreads();             // packed chunk visible before next MMA
        }
    }

    // cross-lane (t-group) argmin reduce; lane with tt==0 owns the row
    #pragma unroll
    for (int m = 0; m < 4; ++m) {
        float v = best[m];
        int id = bidx[m];
        #pragma unroll
        for (int d = 1; d < 4; d <<= 1) {
            float v2 = __shfl_xor_sync(0xffffffffu, v, d);
            int   i2 = __shfl_xor_sync(0xffffffffu, id, d);
            if (v2 < v || (v2 == v && i2 < id)) { v = v2; id = i2; }
        }
        if (tt == 0) {
            int row = r0 + w32 + (m >> 1) * 16 + (m & 1) * 8 + g;
            g_key[half * NROWS + row] = v;
            g_kidx[half * NROWS + row] = (float)(half * 512 + id);
        }
    }
}

// ---------------------------------------------------------------------------
// Kernel 2: z_q, output transpose, ind merge + deterministic fixed-point
// loss accumulation (int64 atomics). Last CTA finalizes + resets counters.
// Grid 1024, 256 threads, 32 rows/CTA.  (Proven R8 version, unchanged.)
// ---------------------------------------------------------------------------
__global__ __launch_bounds__(256)
void zq_kernel(const float* __restrict__ z,
               const float* __restrict__ noise,
               float* __restrict__ out,
               float* __restrict__ out_ind,
               float* __restrict__ out_loss) {
    __shared__ float zt[64][33];     // z[b, d, hw0+w] tile
    __shared__ float zq[32 * 65];
    __shared__ float sred[256];
    int t = threadIdx.x;
    int c = blockIdx.x;
    int b = c >> 5;
    int p = c & 31;
    int r0 = b * 1024 + p * 32;

    int row = t >> 3;
    int seg = t & 7;
    int n = r0 + row;

    // hoisted independent loads (issue before the tile barrier)
    float4 n0 = *(const float4*)&noise[n * 64 + seg * 8];
    float4 n1 = *(const float4*)&noise[n * 64 + seg * 8 + 4];
    float k0 = g_key[n], k1 = g_key[NROWS + n];
    float i0 = g_kidx[n], i1 = g_kidx[NROWS + n];

    // load z tile: 64 d x 32 hw, coalesced over hw
    {
        const float* zb = z + (size_t)b * 65536 + p * 32;
        int w = t & 31, db = t >> 5;
        #pragma unroll
        for (int it = 0; it < 8; ++it) {
            int d = it * 8 + db;
            zt[d][w] = zb[d * 1024 + w];
        }
    }
    __syncthreads();

    float nv[8] = {n0.x, n0.y, n0.z, n0.w, n1.x, n1.y, n1.z, n1.w};
    float zv[8];
    #pragma unroll
    for (int i = 0; i < 8; ++i) zv[i] = zt[seg * 8 + i][row];

    float s = 0.f, xs = 0.f;
    #pragma unroll
    for (int i = 0; i < 8; ++i) { s += nv[i] * nv[i]; xs += zv[i] * zv[i]; }
    s += __shfl_down_sync(0xffffffffu, s, 4, 8);
    xs += __shfl_down_sync(0xffffffffu, xs, 4, 8);
    s += __shfl_down_sync(0xffffffffu, s, 2, 8);
    xs += __shfl_down_sync(0xffffffffu, xs, 2, 8);
    s += __shfl_down_sync(0xffffffffu, s, 1, 8);
    xs += __shfl_down_sync(0xffffffffu, xs, 1, 8);
    float norm2 = __shfl_sync(0xffffffffu, s, 0, 8);
    float x2 = __shfl_sync(0xffffffffu, xs, 0, 8);

    // merge the two code-half candidates (half0 wins ties: lower idx)
    float mk, mi;
    if (k1 < k0) { mk = k1; mi = i1; }
    else         { mk = k0; mi = i0; }
    if (seg == 0) out_ind[n] = mi;

    float dmin = x2 + mk;
    float scale = sqrtf(fmaxf(dmin, 0.f)) / fmaxf(sqrtf(norm2), 1e-9f);

    float part = 0.f;
    #pragma unroll
    for (int i = 0; i < 8; ++i) {
        float q = zv[i] + nv[i] * scale;
        part += q;
        zq[row * 65 + seg * 8 + i] = q;
    }
    sred[t] = part;
    __syncthreads();

    // two independent 128-thread tree reductions (rows 0-15 | rows 16-31)
    for (int off = 64; off > 0; off >>= 1) {
        if ((t & 127) < off) sred[t] += sred[t + off];
        __syncthreads();
    }
    // deterministic fixed-point accumulation of s^2 (scale 2^22)
    if ((t & 127) == 0) {
        float sv = sred[t];
        unsigned long long q =
            (unsigned long long)__double2ll_rn((double)sv * (double)sv * 4194304.0);
        atomicAdd(&g_lacc, q);
    }

    // write out transposed: out[b*65536 + dd*1024 + p*32 + r]
    {
        int dd = t >> 2;
        int rg = t & 3;
        float4 o0, o1;
        o0.x = zq[(rg * 8 + 0) * 65 + dd];
        o0.y = zq[(rg * 8 + 1) * 65 + dd];
        o0.z = zq[(rg * 8 + 2) * 65 + dd];
        o0.w = zq[(rg * 8 + 3) * 65 + dd];
        o1.x = zq[(rg * 8 + 4) * 65 + dd];
        o1.y = zq[(rg * 8 + 5) * 65 + dd];
        o1.z = zq[(rg * 8 + 6) * 65 + dd];
        o1.w = zq[(rg * 8 + 7) * 65 + dd];
        float* op = out + (size_t)b * 65536 + dd * 1024 + p * 32 + rg * 8;
        *(float4*)op = o0;
        *(float4*)(op + 4) = o1;
    }

    // completion protocol: single-thread fence orders this CTA's lacc adds
    __syncthreads();
    if (t == 0) {
        __threadfence();
        int v = atomicAdd(&g_ctr, 1);
        if (v == (int)gridDim.x - 1) {
            unsigned long long tot = atomicAdd(&g_lacc, 0ull);
            *out_loss = (float)((double)tot * (1.0 / 4194304.0) * (1.0 / 33554432.0));
            g_lacc = 0ull;   // reset for next graph replay
            g_ctr = 0;
        }
    }
}

// ---------------------------------------------------------------------------
extern "C" void kernel_launch(void* const* d_in, const int* in_sizes, int n_in,
                              void* d_out, int out_size) {
    const float* z     = (const float*)d_in[0];
    const float* cb    = (const float*)d_in[1];
    const float* noise = (const float*)d_in[2];
    float* out      = (float*)d_out;
    float* out_loss = out + ZQ_ELEMS;
    float* out_ind  = out + ZQ_ELEMS + 1;

    cudaFuncSetAttribute(gemm_argmin_kernel,
                         cudaFuncAttributeMaxDynamicSharedMemorySize, GEMM_SMEM);

    gemm_argmin_kernel<<<128, 512, GEMM_SMEM>>>(z, cb);
    zq_kernel<<<1024, 256>>>(z, noise, out, out_ind, out_loss);
}